// round 13
// baseline (speedup 1.0000x reference)
#include <cuda_runtime.h>
#include <cuda_fp16.h>
#include <math.h>
#include <stdint.h>

// ---------------- problem constants ----------------
#define B_    2
#define S_    2048
#define HID_  2048
#define IN_   4096
#define H_    16
#define NOPE_ 128
#define ROPE_ 64
#define VHD_  128
#define QKD_  192
#define QR_   1536
#define KVR_  512
#define TOK_  (B_*S_)
#define BH_   (B_*H_)
#define EPS_  1e-6f
#define KVO_  (KVR_+ROPE_)   // 576
#define NQKV_ (QR_+KVO_)     // 2112
#define NQKVP_ 2176

// ---------------- scratch ----------------
__device__ float  g_qa  [TOK_*QR_];
__device__ __half g_qah [TOK_*QR_];
__device__ float  g_kvc [TOK_*KVO_];
__device__ __half g_kvnh[TOK_*KVR_];
__device__ __half g_Qfh [BH_*S_*QKD_];
__device__ __half g_Kfh [BH_*S_*QKD_];
__device__ __half g_Vth [BH_*VHD_*S_];             // V^T [bh][d][s]
__device__ __half g_ctxh[TOK_*(H_*VHD_)];
__device__ float  g_cos [TOK_*32];
__device__ float  g_sin [TOK_*32];
__device__ __half g_hsch  [TOK_*IN_];
__device__ __half g_wqkvh [NQKVP_*IN_];
__device__ __half g_wqbh  [(H_*QKD_)*QR_];
__device__ __half g_wkvbh [(H_*(NOPE_+VHD_))*KVR_];
__device__ __half g_woh   [HID_*HID_];

// ---------------- helpers ----------------
__device__ __forceinline__ void mma_f16(float c[4], const uint32_t a[4], const uint32_t b[2]) {
    asm volatile(
        "mma.sync.aligned.m16n8k16.row.col.f32.f16.f16.f32 "
        "{%0,%1,%2,%3}, {%4,%5,%6,%7}, {%8,%9}, {%0,%1,%2,%3};"
        : "+f"(c[0]), "+f"(c[1]), "+f"(c[2]), "+f"(c[3])
        : "r"(a[0]), "r"(a[1]), "r"(a[2]), "r"(a[3]), "r"(b[0]), "r"(b[1]));
}
__device__ __forceinline__ void ldsm_x4(uint32_t& r0, uint32_t& r1, uint32_t& r2, uint32_t& r3,
                                        uint32_t addr) {
    asm volatile("ldmatrix.sync.aligned.m8n8.x4.shared.b16 {%0,%1,%2,%3}, [%4];"
                 : "=r"(r0), "=r"(r1), "=r"(r2), "=r"(r3) : "r"(addr));
}
__device__ __forceinline__ void cp16(uint32_t dst, const void* src) {
    asm volatile("cp.async.cg.shared.global [%0], [%1], 16;\n" :: "r"(dst), "l"(src));
}
__device__ __forceinline__ void cp_commit() {
    asm volatile("cp.async.commit_group;\n" ::: "memory");
}
__device__ __forceinline__ uint32_t h2u(__half2 h) { return *(uint32_t*)&h; }

// ---------------- dense fp16 TB GEMM: 128x128 CTA, 4 warps of 64x64 ----------------
// MODE 0: fp32 out
// MODE 2: split fp32 out (cols < nsplit -> C, rest -> C2)
// MODE 3: qb epilogue — RoPE + [bh][s][QKD] half layout into Ch(=g_Qfh)
// MODE 4: kvb epilogue — K_nope -> g_Kfh, V -> g_Vth (transposed)
#define HBK 32
#define HP  40
#define H_STG (128*HP)      // halves per matrix per stage
#define HSTG  3
#define SMEM_H (HSTG * 2 * H_STG * 2)   // 61440 B

template<int MODE>
__global__ __launch_bounds__(128, 2) void hgemm(
    const __half* __restrict__ A, const __half* __restrict__ B,
    float* __restrict__ C, __half* __restrict__ Ch,
    float* __restrict__ C2, int ldc2, int nsplit,
    int M, int N, int K, int lda, int ldb, int ldc)
{
    extern __shared__ __half hsm[];
    __half* Asm = hsm;
    __half* Bsm = hsm + HSTG * H_STG;
    const uint32_t sA32 = (uint32_t)__cvta_generic_to_shared(Asm);
    const uint32_t sB32 = (uint32_t)__cvta_generic_to_shared(Bsm);

    const int nt = K / HBK;
    const int tid  = threadIdx.x;
    const int lane = tid & 31;
    const int g    = lane >> 2;
    const int tig  = lane & 3;
    const int wid  = tid >> 5;       // 0..3
    const int wm   = wid >> 1;       // 2 warps along M
    const int wn   = wid & 1;        // 2 warps along N
    const int rowBase = blockIdx.y * 128;
    const int colBase = blockIdx.x * 128;

    // loaders: each thread owns one row of A and one row of B (32 halves = 4 cp16)
    const __half* Ap = A + (size_t)(rowBase + tid) * lda;
    const __half* Bp = B + (size_t)(colBase + tid) * ldb;
    const uint32_t a_dst = sA32 + (uint32_t)(tid * HP) * 2u;
    const uint32_t b_dst = sB32 + (uint32_t)(tid * HP) * 2u;

    auto load_stage = [&](int st, int kc) {
        const uint32_t so = (uint32_t)(st * H_STG) * 2u;
        const __half* as = Ap + kc * HBK;
        const __half* bs = Bp + kc * HBK;
        #pragma unroll
        for (int c = 0; c < 4; c++) {
            cp16(a_dst + so + c * 16, as + c * 8);
            cp16(b_dst + so + c * 16, bs + c * 8);
        }
        cp_commit();
    };

    const uint32_t aLB = (uint32_t)(((wm * 64 + (lane & 15)) * HP + (lane >> 4) * 8) * 2);
    const uint32_t bLB = (uint32_t)(((wn * 64 + (lane & 7) + ((lane >> 4) & 1) * 8) * HP
                                     + ((lane >> 3) & 1) * 8) * 2);

    float acc[4][8][4];
    #pragma unroll
    for (int i = 0; i < 4; i++)
        #pragma unroll
        for (int j = 0; j < 8; j++)
            #pragma unroll
            for (int q = 0; q < 4; q++) acc[i][j][q] = 0.f;

    // prologue: 2 stages in flight
    #pragma unroll
    for (int s = 0; s < HSTG - 1; s++) {
        if (s < nt) load_stage(s, s);
        else        cp_commit();
    }

    for (int t = 0; t < nt; t++) {
        asm volatile("cp.async.wait_group 1;\n" ::: "memory");
        __syncthreads();

        const int tn = t + HSTG - 1;
        if (tn < nt) load_stage(tn % HSTG, tn);
        else         cp_commit();

        const uint32_t stoff = (uint32_t)((t % HSTG) * H_STG) * 2u;
        const uint32_t aSt = sA32 + stoff + aLB;
        const uint32_t bSt = sB32 + stoff + bLB;

        #pragma unroll
        for (int ks = 0; ks < 2; ks++) {
            const uint32_t kby = (uint32_t)(ks * 32);
            uint32_t afr[4][4], bfr[8][2];
            #pragma unroll
            for (int fm = 0; fm < 4; fm++)
                ldsm_x4(afr[fm][0], afr[fm][1], afr[fm][2], afr[fm][3],
                        aSt + (uint32_t)(fm * 16 * HP) * 2u + kby);
            #pragma unroll
            for (int fp = 0; fp < 4; fp++)
                ldsm_x4(bfr[2*fp][0], bfr[2*fp][1], bfr[2*fp+1][0], bfr[2*fp+1][1],
                        bSt + (uint32_t)(fp * 16 * HP) * 2u + kby);
            #pragma unroll
            for (int fm = 0; fm < 4; fm++)
                #pragma unroll
                for (int fn = 0; fn < 8; fn++)
                    mma_f16(acc[fm][fn], afr[fm], bfr[fn]);
        }
    }

    #pragma unroll
    for (int fm = 0; fm < 4; fm++) {
        #pragma unroll
        for (int fn = 0; fn < 8; fn++) {
            const int row = rowBase + wm * 64 + fm * 16 + g;
            const int col = colBase + wn * 64 + fn * 8 + tig * 2;   // always even
            if (col >= N) continue;
            const float a0 = acc[fm][fn][0], a1 = acc[fm][fn][1];
            const float a2 = acc[fm][fn][2], a3 = acc[fm][fn][3];

            if (MODE == 0) {
                *(float2*)&C[(size_t)row * ldc + col]       = make_float2(a0, a1);
                *(float2*)&C[(size_t)(row + 8) * ldc + col] = make_float2(a2, a3);
            } else if (MODE == 2) {
                if (col < nsplit) {
                    *(float2*)&C[(size_t)row * ldc + col]       = make_float2(a0, a1);
                    *(float2*)&C[(size_t)(row + 8) * ldc + col] = make_float2(a2, a3);
                } else {
                    const int c2 = col - nsplit;
                    *(float2*)&C2[(size_t)row * ldc2 + c2]       = make_float2(a0, a1);
                    *(float2*)&C2[(size_t)(row + 8) * ldc2 + c2] = make_float2(a2, a3);
                }
            } else if (MODE == 3) {
                const int h = col / QKD_, d = col - h * QKD_;
                #pragma unroll
                for (int rr = 0; rr < 2; rr++) {
                    const int tok = row + rr * 8;
                    const int b = tok >> 11, s = tok & (S_-1);
                    __half* dst = Ch + (((size_t)(b * H_ + h) * S_ + s) * QKD_ + d);
                    const float e = rr ? a2 : a0, o = rr ? a3 : a1;
                    __half2 hv;
                    if (d < NOPE_) {
                        hv = __floats2half2_rn(e, o);
                    } else {
                        const int j = (d - NOPE_) >> 1;
                        const float cc = g_cos[tok * 32 + j], ss = g_sin[tok * 32 + j];
                        hv = __floats2half2_rn(e * cc - o * ss, o * cc + e * ss);
                    }
                    *(__half2*)dst = hv;
                }
            } else {  // MODE 4
                const int h = col >> 8, d = col & 255;
                #pragma unroll
                for (int rr = 0; rr < 2; rr++) {
                    const int tok = row + rr * 8;
                    const int b = tok >> 11, s = tok & (S_-1);
                    const int bh = b * H_ + h;
                    const float e = rr ? a2 : a0, o = rr ? a3 : a1;
                    if (d < NOPE_) {
                        *(__half2*)&g_Kfh[((size_t)bh * S_ + s) * QKD_ + d] =
                            __floats2half2_rn(e, o);
                    } else {
                        const int dd = d - NOPE_;
                        __half* vb = g_Vth + ((size_t)bh * VHD_ + dd) * S_ + s;
                        vb[0]  = __float2half(e);
                        vb[S_] = __float2half(o);
                    }
                }
            }
        }
    }
}

// ---------------- fused flash attention (ldmatrix mainloop) ----------------
#define FBQ 128
#define FBK 64
#define FQP 200
#define FVP 72
#define FQ_SZ (FBQ*FQP)
#define FK_SZ (FBK*FQP)
#define FV_SZ (VHD_*FVP)
#define FSMEM ((FQ_SZ + 2*FK_SZ + 2*FV_SZ) * 2)

__global__ __launch_bounds__(256, 1) void flash_attn(float scale)
{
    extern __shared__ __half fsm[];
    __half* Qs  = fsm;
    __half* Ks0 = Qs + FQ_SZ;
    __half* Vs0 = Ks0 + 2 * FK_SZ;
    const uint32_t sQ = (uint32_t)__cvta_generic_to_shared(Qs);
    const uint32_t sK = (uint32_t)__cvta_generic_to_shared(Ks0);
    const uint32_t sV = (uint32_t)__cvta_generic_to_shared(Vs0);

    const int qt = (int)(gridDim.x - 1 - blockIdx.x);
    const int bh = blockIdx.y;
    const int qbase = qt * FBQ;
    const int tid = threadIdx.x;
    const int wid = tid >> 5, lane = tid & 31, g = lane >> 2, tig = lane & 3;
    const int qr0 = wid * 16;

    const __half* Qg = g_Qfh + ((size_t)bh * S_ + qbase) * QKD_;
    const __half* Kg = g_Kfh + (size_t)bh * S_ * QKD_;
    const __half* Vg = g_Vth + (size_t)bh * VHD_ * S_;

    {
        int r = tid >> 1, off = (tid & 1) * 96;
        const __half* src = Qg + (size_t)r * QKD_ + off;
        uint32_t dst = sQ + (uint32_t)(r * FQP + off) * 2u;
        #pragma unroll
        for (int c = 0; c < 12; c++) cp16(dst + c * 16, src + c * 8);
    }
    auto loadKV = [&](int st, int kt) {
        const int kbase = kt * FBK;
        {   int r = tid >> 2, off = (tid & 3) * 48;
            const __half* src = Kg + (size_t)(kbase + r) * QKD_ + off;
            uint32_t dst = sK + (uint32_t)(st * FK_SZ + r * FQP + off) * 2u;
            #pragma unroll
            for (int c = 0; c < 6; c++) cp16(dst + c * 16, src + c * 8);
        }
        {   int r = tid >> 1, off = (tid & 1) * 32;
            const __half* src = Vg + (size_t)r * S_ + kbase + off;
            uint32_t dst = sV + (uint32_t)(st * FV_SZ + r * FVP + off) * 2u;
            #pragma unroll
            for (int c = 0; c < 4; c++) cp16(dst + c * 16, src + c * 8);
        }
        cp_commit();
    };

    const int ktmax = (qbase + FBQ - 1) / FBK;
    loadKV(0, 0);

    float oacc[16][4];
    #pragma unroll
    for (int i = 0; i < 16; i++)
        #pragma unroll
        for (int j = 0; j < 4; j++) oacc[i][j] = 0.f;
    float sm0 = -1e30f, sm1 = -1e30f, l0 = 0.f, l1 = 0.f;

    const int row0 = qbase + qr0 + g;
    const int row1 = row0 + 8;

    const uint32_t aQB = sQ + (uint32_t)(((qr0 + (lane & 15)) * FQP + (lane >> 4) * 8) * 2);
    const uint32_t bRow = (uint32_t)((lane & 7) + ((lane >> 4) & 1) * 8);
    const uint32_t bCol = (uint32_t)(((lane >> 3) & 1) * 8);
    const uint32_t bKB = (uint32_t)((bRow * FQP + bCol) * 2);
    const uint32_t bVB = (uint32_t)((bRow * FVP + bCol) * 2);

    for (int kt = 0; kt <= ktmax; kt++) {
        const int st = kt & 1;
        if (kt < ktmax) {
            loadKV(st ^ 1, kt + 1);
            asm volatile("cp.async.wait_group 1;\n" ::: "memory");
        } else {
            asm volatile("cp.async.wait_group 0;\n" ::: "memory");
        }
        __syncthreads();

        const int kbase = kt * FBK;
        if (kbase <= qbase + qr0 + 15) {
            const uint32_t kSt = sK + (uint32_t)(st * FK_SZ) * 2u + bKB;
            const uint32_t vSt = sV + (uint32_t)(st * FV_SZ) * 2u + bVB;

            float sacc[8][4];
            #pragma unroll
            for (int nb = 0; nb < 8; nb++)
                #pragma unroll
                for (int j = 0; j < 4; j++) sacc[nb][j] = 0.f;

            #pragma unroll
            for (int kc = 0; kc < 12; kc++) {
                const uint32_t kby = (uint32_t)(kc * 32);
                uint32_t a[4];
                ldsm_x4(a[0], a[1], a[2], a[3], aQB + kby);
                uint32_t b[8][2];
                #pragma unroll
                for (int np = 0; np < 4; np++)
                    ldsm_x4(b[2*np][0], b[2*np][1], b[2*np+1][0], b[2*np+1][1],
                            kSt + (uint32_t)(np * 16 * FQP) * 2u + kby);
                #pragma unroll
                for (int nb = 0; nb < 8; nb++)
                    mma_f16(sacc[nb], a, b[nb]);
            }

            const bool need_mask = (kbase + FBK - 1) > (qbase + qr0);
            #pragma unroll
            for (int nb = 0; nb < 8; nb++) {
                const int c0 = kbase + nb * 8 + 2 * tig, c1 = c0 + 1;
                sacc[nb][0] *= scale; sacc[nb][1] *= scale;
                sacc[nb][2] *= scale; sacc[nb][3] *= scale;
                if (need_mask) {
                    if (c0 > row0) sacc[nb][0] = -1e30f;
                    if (c1 > row0) sacc[nb][1] = -1e30f;
                    if (c0 > row1) sacc[nb][2] = -1e30f;
                    if (c1 > row1) sacc[nb][3] = -1e30f;
                }
            }

            float mx0 = -1e30f, mx1 = -1e30f;
            #pragma unroll
            for (int nb = 0; nb < 8; nb++) {
                mx0 = fmaxf(mx0, fmaxf(sacc[nb][0], sacc[nb][1]));
                mx1 = fmaxf(mx1, fmaxf(sacc[nb][2], sacc[nb][3]));
            }
            mx0 = fmaxf(mx0, __shfl_xor_sync(0xFFFFFFFFu, mx0, 1));
            mx0 = fmaxf(mx0, __shfl_xor_sync(0xFFFFFFFFu, mx0, 2));
            mx1 = fmaxf(mx1, __shfl_xor_sync(0xFFFFFFFFu, mx1, 1));
            mx1 = fmaxf(mx1, __shfl_xor_sync(0xFFFFFFFFu, mx1, 2));

            const float mn0 = fmaxf(sm0, mx0), mn1 = fmaxf(sm1, mx1);
            const float al0 = __expf(sm0 - mn0), al1 = __expf(sm1 - mn1);
            sm0 = mn0; sm1 = mn1;

            uint32_t pA[8], pB[8];
            float ps0 = 0.f, ps1 = 0.f;
            #pragma unroll
            for (int nb = 0; nb < 8; nb++) {
                const float e0 = __expf(sacc[nb][0] - mn0);
                const float e1 = __expf(sacc[nb][1] - mn0);
                const float e2 = __expf(sacc[nb][2] - mn1);
                const float e3 = __expf(sacc[nb][3] - mn1);
                ps0 += e0 + e1; ps1 += e2 + e3;
                pA[nb] = h2u(__floats2half2_rn(e0, e1));
                pB[nb] = h2u(__floats2half2_rn(e2, e3));
            }
            l0 = l0 * al0 + ps0;
            l1 = l1 * al1 + ps1;

            #pragma unroll
            for (int nb2 = 0; nb2 < 16; nb2++) {
                oacc[nb2][0] *= al0; oacc[nb2][1] *= al0;
                oacc[nb2][2] *= al1; oacc[nb2][3] *= al1;
            }

            #pragma unroll
            for (int kc = 0; kc < 4; kc++) {
                uint32_t a[4] = { pA[2*kc], pB[2*kc], pA[2*kc+1], pB[2*kc+1] };
                const uint32_t kby = (uint32_t)(kc * 32);
                uint32_t bv[16][2];
                #pragma unroll
                for (int np = 0; np < 8; np++)
                    ldsm_x4(bv[2*np][0], bv[2*np][1], bv[2*np+1][0], bv[2*np+1][1],
                            vSt + (uint32_t)(np * 16 * FVP) * 2u + kby);
                #pragma unroll
                for (int nb2 = 0; nb2 < 16; nb2++)
                    mma_f16(oacc[nb2], a, bv[nb2]);
            }
        }
        __syncthreads();
    }

    l0 += __shfl_xor_sync(0xFFFFFFFFu, l0, 1);
    l0 += __shfl_xor_sync(0xFFFFFFFFu, l0, 2);
    l1 += __shfl_xor_sync(0xFFFFFFFFu, l1, 1);
    l1 += __shfl_xor_sync(0xFFFFFFFFu, l1, 2);
    const float inv0 = 1.f / l0, inv1 = 1.f / l1;

    const int b = bh / H_, h = bh % H_;
    __half* out0 = g_ctxh + (size_t)(b * S_ + row0) * (H_*VHD_) + h * VHD_;
    __half* out1 = out0 + (size_t)8 * (H_*VHD_);
    #pragma unroll
    for (int nb2 = 0; nb2 < 16; nb2++) {
        const int d = nb2 * 8 + 2 * tig;
        *(__half2*)(out0 + d) = __floats2half2_rn(oacc[nb2][0] * inv0, oacc[nb2][1] * inv0);
        *(__half2*)(out1 + d) = __floats2half2_rn(oacc[nb2][2] * inv1, oacc[nb2][3] * inv1);
    }
}

// ---------------- converts ----------------
__global__ void cvt_h(const float* __restrict__ src, __half* __restrict__ dst, int n4) {
    int i = blockIdx.x * blockDim.x + threadIdx.x;
    if (i >= n4) return;
    float4 v = ((const float4*)src)[i];
    ((__half2*)dst)[2*i]   = __floats2half2_rn(v.x, v.y);
    ((__half2*)dst)[2*i+1] = __floats2half2_rn(v.z, v.w);
}

__global__ void transpose_h(const float* __restrict__ src, __half* __restrict__ dst,
                            int K, int N, int Npad)
{
    __shared__ float tile[32][33];
    const int k0 = blockIdx.y * 32, n0 = blockIdx.x * 32;
    const int tx = threadIdx.x, ty = threadIdx.y;
    #pragma unroll
    for (int i = ty; i < 32; i += 8) {
        int k = k0 + i, n = n0 + tx;
        tile[i][tx] = (k < K && n < N) ? src[(size_t)k * N + n] : 0.f;
    }
    __syncthreads();
    #pragma unroll
    for (int i = ty; i < 32; i += 8) {
        int n = n0 + i, k = k0 + tx;
        if (n < Npad && k < K) dst[(size_t)n * K + k] = __float2half(tile[tx][i]);
    }
}

// ---------------- fused rmsnorm ----------------
__device__ __forceinline__ float block_reduce_sum(float v, float* sbuf) {
    int tid = threadIdx.x;
    sbuf[tid] = v; __syncthreads();
    #pragma unroll
    for (int s = 128; s > 0; s >>= 1) {
        if (tid < s) sbuf[tid] = sbuf[tid] + sbuf[tid + s];
        __syncthreads();
    }
    float r = sbuf[0]; __syncthreads();
    return r;
}

__global__ __launch_bounds__(256) void rms_both(const float* __restrict__ q_ln,
                                                const float* __restrict__ kv_ln)
{
    __shared__ float sbuf[256];
    const int row = blockIdx.x;
    const float* xr;
    const float* w;
    __half* yr;
    int n;
    if (row < TOK_) {
        xr = g_qa + (size_t)row * QR_; w = q_ln; yr = g_qah + (size_t)row * QR_; n = QR_;
    } else {
        int r = row - TOK_;
        xr = g_kvc + (size_t)r * KVO_; w = kv_ln; yr = g_kvnh + (size_t)r * KVR_; n = KVR_;
    }
    float acc = 0.f;
    for (int j = threadIdx.x; j < n; j += 256) { float v = xr[j]; acc += v * v; }
    float tot = block_reduce_sum(acc, sbuf);
    float scale = rsqrtf(tot / (float)n + EPS_);
    for (int j = threadIdx.x; j < n; j += 256) yr[j] = __float2half(xr[j] * scale * w[j]);
}

// ---------------- RoPE table + K-rope broadcast ----------------
__global__ void build_cs(const int* __restrict__ pos) {
    int idx = blockIdx.x * blockDim.x + threadIdx.x;
    if (idx >= TOK_ * 32) return;
    int j = idx & 31, tok = idx >> 5;
    float inv = powf(10000.f, -((float)(2 * j)) / 64.f);
    float ang = (float)pos[tok] * inv;
    g_cos[idx] = cosf(ang);
    g_sin[idx] = sinf(ang);
}

__global__ void rope_k() {
    int idx = blockIdx.x * blockDim.x + threadIdx.x;
    if (idx >= BH_ * S_ * 32) return;
    int j  = idx & 31;
    int r  = idx >> 5;
    int s  = r % S_;
    int bh = r / S_;
    int b  = bh / H_;
    int tok = b * S_ + s;
    const float* pb = g_kvc + (size_t)tok * KVO_ + KVR_;
    float c = g_cos[tok * 32 + j], sn = g_sin[tok * 32 + j];
    float ev = pb[2*j], ov = pb[2*j + 1];
    *(__half2*)&g_Kfh[((size_t)bh * S_ + s) * QKD_ + NOPE_ + 2*j] =
        __floats2half2_rn(ev * c - ov * sn, ov * c + ev * sn);
}

// ---------------- launcher ----------------
extern "C" void kernel_launch(void* const* d_in, const int* in_sizes, int n_in,
                              void* d_out, int out_size)
{
    const float* hs    = (const float*)d_in[0];
    const float* Wq_a  = (const float*)d_in[1];
    const float* q_ln  = (const float*)d_in[2];
    const float* Wq_b  = (const float*)d_in[3];
    const float* Wkv_a = (const float*)d_in[4];
    const float* kv_ln = (const float*)d_in[5];
    const float* Wkv_b = (const float*)d_in[6];
    const float* Wo    = (const float*)d_in[7];
    const int*   pos   = (const int*)  d_in[8];
    float* out = (float*)d_out;

    float *p_qa, *p_kvc;
    __half *p_qah, *p_kvnh, *p_Qfh, *p_ctxh;
    __half *p_hsch, *p_wqkvh, *p_wqbh, *p_wkvbh, *p_woh;
    cudaGetSymbolAddress((void**)&p_qa,    g_qa);
    cudaGetSymbolAddress((void**)&p_qah,   g_qah);
    cudaGetSymbolAddress((void**)&p_kvc,   g_kvc);
    cudaGetSymbolAddress((void**)&p_kvnh,  g_kvnh);
    cudaGetSymbolAddress((void**)&p_Qfh,   g_Qfh);
    cudaGetSymbolAddress((void**)&p_ctxh,  g_ctxh);
    cudaGetSymbolAddress((void**)&p_hsch,  g_hsch);
    cudaGetSymbolAddress((void**)&p_wqkvh, g_wqkvh);
    cudaGetSymbolAddress((void**)&p_wqbh,  g_wqbh);
    cudaGetSymbolAddress((void**)&p_wkvbh, g_wkvbh);
    cudaGetSymbolAddress((void**)&p_woh,   g_woh);

    static bool attr_done = false;
    if (!attr_done) {
        cudaFuncSetAttribute(hgemm<0>, cudaFuncAttributeMaxDynamicSharedMemorySize, SMEM_H);
        cudaFuncSetAttribute(hgemm<2>, cudaFuncAttributeMaxDynamicSharedMemorySize, SMEM_H);
        cudaFuncSetAttribute(hgemm<3>, cudaFuncAttributeMaxDynamicSharedMemorySize, SMEM_H);
        cudaFuncSetAttribute(hgemm<4>, cudaFuncAttributeMaxDynamicSharedMemorySize, SMEM_H);
        cudaFuncSetAttribute(flash_attn, cudaFuncAttributeMaxDynamicSharedMemorySize, FSMEM);
        attr_done = true;
    }

    // converts
    cvt_h<<<(TOK_*IN_/4 + 255)/256, 256>>>(hs, p_hsch, TOK_*IN_/4);
    dim3 tb(32, 8);
    transpose_h<<<dim3(QR_/32, IN_/32), tb>>>(Wq_a, p_wqkvh, IN_, QR_, QR_);
    transpose_h<<<dim3((KVO_+31)/32, IN_/32), tb>>>(Wkv_a, p_wqkvh + (size_t)QR_*IN_,
                                                    IN_, KVO_, KVO_);
    transpose_h<<<dim3((H_*QKD_)/32, QR_/32), tb>>>(Wq_b, p_wqbh, QR_, H_*QKD_, H_*QKD_);
    transpose_h<<<dim3((H_*(NOPE_+VHD_))/32, KVR_/32), tb>>>(Wkv_b, p_wkvbh,
                                                             KVR_, H_*(NOPE_+VHD_), H_*(NOPE_+VHD_));
    transpose_h<<<dim3(HID_/32, HID_/32), tb>>>(Wo, p_woh, HID_, HID_, HID_);
    build_cs<<<(TOK_*32 + 255)/256, 256>>>(pos);

    // merged qa + kva projection
    hgemm<2><<<dim3(NQKVP_/128, TOK_/128), 128, SMEM_H>>>(
        p_hsch, p_wqkvh, p_qa, nullptr, p_kvc, KVO_, QR_,
        TOK_, NQKV_, IN_, IN_, IN_, QR_);

    rms_both<<<2*TOK_, 256>>>(q_ln, kv_ln);
    rope_k<<<(BH_*S_*32 + 255)/256, 256>>>();

    // qb projection with fused RoPE + layout (writes g_Qfh)
    hgemm<3><<<dim3((H_*QKD_)/128, TOK_/128), 128, SMEM_H>>>(
        p_qah, p_wqbh, nullptr, p_Qfh, nullptr, 0, 0,
        TOK_, H_*QKD_, QR_, QR_, QR_, H_*QKD_);

    // kvb projection with fused K/V scatter
    hgemm<4><<<dim3((H_*(NOPE_+VHD_))/128, TOK_/128), 128, SMEM_H>>>(
        p_kvnh, p_wkvbh, nullptr, nullptr, nullptr, 0, 0,
        TOK_, H_*(NOPE_+VHD_), KVR_, KVR_, KVR_, H_*(NOPE_+VHD_));

    // fused attention
    float scale = 1.f / sqrtf((float)QKD_);
    flash_attn<<<dim3(S_/FBQ, BH_), 256, FSMEM>>>(scale);

    // output projection
    hgemm<0><<<dim3(HID_/128, TOK_/128), 128, SMEM_H>>>(
        p_ctxh, p_woh, out, nullptr, nullptr, 0, 0,
        TOK_, HID_, HID_, HID_, HID_, HID_);
}

// round 14
// speedup vs baseline: 1.0319x; 1.0319x over previous
#include <cuda_runtime.h>
#include <cuda_fp16.h>
#include <math.h>
#include <stdint.h>

// ---------------- problem constants ----------------
#define B_    2
#define S_    2048
#define HID_  2048
#define IN_   4096
#define H_    16
#define NOPE_ 128
#define ROPE_ 64
#define VHD_  128
#define QKD_  192
#define QR_   1536
#define KVR_  512
#define TOK_  (B_*S_)
#define BH_   (B_*H_)
#define EPS_  1e-6f
#define KVO_  (KVR_+ROPE_)   // 576
#define NQKV_ (QR_+KVO_)     // 2112
#define NQKVP_ 2176

// ---------------- scratch ----------------
__device__ float  g_qa  [TOK_*QR_];
__device__ __half g_qah [TOK_*QR_];
__device__ float  g_kvc [TOK_*KVO_];
__device__ __half g_kvnh[TOK_*KVR_];
__device__ __half g_Qfh [BH_*S_*QKD_];
__device__ __half g_Kfh [BH_*S_*QKD_];
__device__ __half g_Vth [BH_*VHD_*S_];             // V^T [bh][d][s]
__device__ __half g_ctxh[TOK_*(H_*VHD_)];
__device__ float  g_cos [TOK_*32];
__device__ float  g_sin [TOK_*32];
__device__ __half g_hsch  [TOK_*IN_];
__device__ __half g_wqkvh [NQKVP_*IN_];
__device__ __half g_wqbh  [(H_*QKD_)*QR_];
__device__ __half g_wkvbh [(H_*(NOPE_+VHD_))*KVR_];
__device__ __half g_woh   [HID_*HID_];

// ---------------- helpers ----------------
__device__ __forceinline__ void mma_f16(float c[4], const uint32_t a[4], const uint32_t b[2]) {
    asm volatile(
        "mma.sync.aligned.m16n8k16.row.col.f32.f16.f16.f32 "
        "{%0,%1,%2,%3}, {%4,%5,%6,%7}, {%8,%9}, {%0,%1,%2,%3};"
        : "+f"(c[0]), "+f"(c[1]), "+f"(c[2]), "+f"(c[3])
        : "r"(a[0]), "r"(a[1]), "r"(a[2]), "r"(a[3]), "r"(b[0]), "r"(b[1]));
}
__device__ __forceinline__ void ldsm_x4(uint32_t& r0, uint32_t& r1, uint32_t& r2, uint32_t& r3,
                                        uint32_t addr) {
    asm volatile("ldmatrix.sync.aligned.m8n8.x4.shared.b16 {%0,%1,%2,%3}, [%4];"
                 : "=r"(r0), "=r"(r1), "=r"(r2), "=r"(r3) : "r"(addr));
}
__device__ __forceinline__ void cp16(uint32_t dst, const void* src) {
    asm volatile("cp.async.cg.shared.global [%0], [%1], 16;\n" :: "r"(dst), "l"(src));
}
__device__ __forceinline__ void cp_commit() {
    asm volatile("cp.async.commit_group;\n" ::: "memory");
}
__device__ __forceinline__ uint32_t h2u(__half2 h) { return *(uint32_t*)&h; }

// ---------------- dense fp16 TB GEMM: 128x128 CTA, 8 warps of 64x32, BK=64 ----------------
// MODE 0: fp32 out
// MODE 2: split fp32 out (cols < nsplit -> C, rest -> C2)
// MODE 3: qb epilogue — RoPE + [bh][s][QKD] half layout into Ch(=g_Qfh)
// MODE 4: kvb epilogue — K_nope -> g_Kfh, V -> g_Vth (transposed)
#define HBK 64
#define HP  72                          // pitch (halves); 144B rows, conflict-free LDSM
#define H_STG (128*HP)                  // halves per matrix per stage
#define HSTG  3
#define SMEM_H (HSTG * 2 * H_STG * 2)   // 110592 B

template<int MODE>
__global__ __launch_bounds__(256, 2) void hgemm(
    const __half* __restrict__ A, const __half* __restrict__ B,
    float* __restrict__ C, __half* __restrict__ Ch,
    float* __restrict__ C2, int ldc2, int nsplit,
    int M, int N, int K, int lda, int ldb, int ldc)
{
    extern __shared__ __half hsm[];
    __half* Asm = hsm;
    __half* Bsm = hsm + HSTG * H_STG;
    const uint32_t sA32 = (uint32_t)__cvta_generic_to_shared(Asm);
    const uint32_t sB32 = (uint32_t)__cvta_generic_to_shared(Bsm);

    const int nt = K / HBK;
    const int tid  = threadIdx.x;
    const int lane = tid & 31;
    const int g    = lane >> 2;
    const int tig  = lane & 3;
    const int wid  = tid >> 5;
    const int wm   = wid & 1;        // 2 warps along M
    const int wn   = wid >> 1;       // 4 warps along N
    const int rowBase = blockIdx.y * 128;
    const int colBase = blockIdx.x * 128;

    // loaders: 2 threads/row, 32 halves each (4 cp16) for A and B
    const int r  = tid >> 1;
    const int co = (tid & 1) << 5;   // 0 or 32 halves
    const __half* Ap = A + (size_t)(rowBase + r) * lda + co;
    const __half* Bp = B + (size_t)(colBase + r) * ldb + co;
    const uint32_t a_dst = sA32 + (uint32_t)(r * HP + co) * 2u;
    const uint32_t b_dst = sB32 + (uint32_t)(r * HP + co) * 2u;

    auto load_stage = [&](int st, int kc) {
        const uint32_t so = (uint32_t)(st * H_STG) * 2u;
        const __half* as = Ap + kc * HBK;
        const __half* bs = Bp + kc * HBK;
        #pragma unroll
        for (int c = 0; c < 4; c++) {
            cp16(a_dst + so + c * 16, as + c * 8);
            cp16(b_dst + so + c * 16, bs + c * 8);
        }
        cp_commit();
    };

    const uint32_t aLB = (uint32_t)(((wm * 64 + (lane & 15)) * HP + (lane >> 4) * 8) * 2);
    const uint32_t bLB = (uint32_t)(((wn * 32 + (lane & 7) + ((lane >> 4) & 1) * 8) * HP
                                     + ((lane >> 3) & 1) * 8) * 2);

    float acc[4][4][4];
    #pragma unroll
    for (int i = 0; i < 4; i++)
        #pragma unroll
        for (int j = 0; j < 4; j++)
            #pragma unroll
            for (int q = 0; q < 4; q++) acc[i][j][q] = 0.f;

    #pragma unroll
    for (int s = 0; s < HSTG - 1; s++) {
        if (s < nt) load_stage(s, s);
        else        cp_commit();
    }

    for (int t = 0; t < nt; t++) {
        asm volatile("cp.async.wait_group 1;\n" ::: "memory");
        __syncthreads();

        const int tn = t + HSTG - 1;
        if (tn < nt) load_stage(tn % HSTG, tn);
        else         cp_commit();

        const uint32_t stoff = (uint32_t)((t % HSTG) * H_STG) * 2u;
        const uint32_t aSt = sA32 + stoff + aLB;
        const uint32_t bSt = sB32 + stoff + bLB;

        #pragma unroll
        for (int ks = 0; ks < 4; ks++) {
            const uint32_t kby = (uint32_t)(ks * 32);   // 16 halves per step
            uint32_t afr[4][4], bfr[4][2];
            #pragma unroll
            for (int fm = 0; fm < 4; fm++)
                ldsm_x4(afr[fm][0], afr[fm][1], afr[fm][2], afr[fm][3],
                        aSt + (uint32_t)(fm * 16 * HP) * 2u + kby);
            #pragma unroll
            for (int fp = 0; fp < 2; fp++)
                ldsm_x4(bfr[2*fp][0], bfr[2*fp][1], bfr[2*fp+1][0], bfr[2*fp+1][1],
                        bSt + (uint32_t)(fp * 16 * HP) * 2u + kby);
            #pragma unroll
            for (int fm = 0; fm < 4; fm++)
                #pragma unroll
                for (int fn = 0; fn < 4; fn++)
                    mma_f16(acc[fm][fn], afr[fm], bfr[fn]);
        }
    }

    #pragma unroll
    for (int fm = 0; fm < 4; fm++) {
        #pragma unroll
        for (int fn = 0; fn < 4; fn++) {
            const int row = rowBase + wm * 64 + fm * 16 + g;
            const int col = colBase + wn * 32 + fn * 8 + tig * 2;   // always even
            if (col >= N) continue;
            const float a0 = acc[fm][fn][0], a1 = acc[fm][fn][1];
            const float a2 = acc[fm][fn][2], a3 = acc[fm][fn][3];

            if (MODE == 0) {
                *(float2*)&C[(size_t)row * ldc + col]       = make_float2(a0, a1);
                *(float2*)&C[(size_t)(row + 8) * ldc + col] = make_float2(a2, a3);
            } else if (MODE == 2) {
                if (col < nsplit) {
                    *(float2*)&C[(size_t)row * ldc + col]       = make_float2(a0, a1);
                    *(float2*)&C[(size_t)(row + 8) * ldc + col] = make_float2(a2, a3);
                } else {
                    const int c2 = col - nsplit;
                    *(float2*)&C2[(size_t)row * ldc2 + c2]       = make_float2(a0, a1);
                    *(float2*)&C2[(size_t)(row + 8) * ldc2 + c2] = make_float2(a2, a3);
                }
            } else if (MODE == 3) {
                const int h = col / QKD_, d = col - h * QKD_;
                #pragma unroll
                for (int rr = 0; rr < 2; rr++) {
                    const int tok = row + rr * 8;
                    const int b = tok >> 11, s = tok & (S_-1);
                    __half* dst = Ch + (((size_t)(b * H_ + h) * S_ + s) * QKD_ + d);
                    const float e = rr ? a2 : a0, o = rr ? a3 : a1;
                    __half2 hv;
                    if (d < NOPE_) {
                        hv = __floats2half2_rn(e, o);
                    } else {
                        const int j = (d - NOPE_) >> 1;
                        const float cc = g_cos[tok * 32 + j], ss = g_sin[tok * 32 + j];
                        hv = __floats2half2_rn(e * cc - o * ss, o * cc + e * ss);
                    }
                    *(__half2*)dst = hv;
                }
            } else {  // MODE 4
                const int h = col >> 8, d = col & 255;
                #pragma unroll
                for (int rr = 0; rr < 2; rr++) {
                    const int tok = row + rr * 8;
                    const int b = tok >> 11, s = tok & (S_-1);
                    const int bh = b * H_ + h;
                    const float e = rr ? a2 : a0, o = rr ? a3 : a1;
                    if (d < NOPE_) {
                        *(__half2*)&g_Kfh[((size_t)bh * S_ + s) * QKD_ + d] =
                            __floats2half2_rn(e, o);
                    } else {
                        const int dd = d - NOPE_;
                        __half* vb = g_Vth + ((size_t)bh * VHD_ + dd) * S_ + s;
                        vb[0]  = __float2half(e);
                        vb[S_] = __float2half(o);
                    }
                }
            }
        }
    }
}

// ---------------- fused flash attention (ldmatrix mainloop) ----------------
#define FBQ 128
#define FBK 64
#define FQP 200
#define FVP 72
#define FQ_SZ (FBQ*FQP)
#define FK_SZ (FBK*FQP)
#define FV_SZ (VHD_*FVP)
#define FSMEM ((FQ_SZ + 2*FK_SZ + 2*FV_SZ) * 2)

__global__ __launch_bounds__(256, 1) void flash_attn(float scale)
{
    extern __shared__ __half fsm[];
    __half* Qs  = fsm;
    __half* Ks0 = Qs + FQ_SZ;
    __half* Vs0 = Ks0 + 2 * FK_SZ;
    const uint32_t sQ = (uint32_t)__cvta_generic_to_shared(Qs);
    const uint32_t sK = (uint32_t)__cvta_generic_to_shared(Ks0);
    const uint32_t sV = (uint32_t)__cvta_generic_to_shared(Vs0);

    const int qt = (int)(gridDim.x - 1 - blockIdx.x);
    const int bh = blockIdx.y;
    const int qbase = qt * FBQ;
    const int tid = threadIdx.x;
    const int wid = tid >> 5, lane = tid & 31, g = lane >> 2, tig = lane & 3;
    const int qr0 = wid * 16;

    const __half* Qg = g_Qfh + ((size_t)bh * S_ + qbase) * QKD_;
    const __half* Kg = g_Kfh + (size_t)bh * S_ * QKD_;
    const __half* Vg = g_Vth + (size_t)bh * VHD_ * S_;

    {
        int r = tid >> 1, off = (tid & 1) * 96;
        const __half* src = Qg + (size_t)r * QKD_ + off;
        uint32_t dst = sQ + (uint32_t)(r * FQP + off) * 2u;
        #pragma unroll
        for (int c = 0; c < 12; c++) cp16(dst + c * 16, src + c * 8);
    }
    auto loadKV = [&](int st, int kt) {
        const int kbase = kt * FBK;
        {   int r = tid >> 2, off = (tid & 3) * 48;
            const __half* src = Kg + (size_t)(kbase + r) * QKD_ + off;
            uint32_t dst = sK + (uint32_t)(st * FK_SZ + r * FQP + off) * 2u;
            #pragma unroll
            for (int c = 0; c < 6; c++) cp16(dst + c * 16, src + c * 8);
        }
        {   int r = tid >> 1, off = (tid & 1) * 32;
            const __half* src = Vg + (size_t)r * S_ + kbase + off;
            uint32_t dst = sV + (uint32_t)(st * FV_SZ + r * FVP + off) * 2u;
            #pragma unroll
            for (int c = 0; c < 4; c++) cp16(dst + c * 16, src + c * 8);
        }
        cp_commit();
    };

    const int ktmax = (qbase + FBQ - 1) / FBK;
    loadKV(0, 0);

    float oacc[16][4];
    #pragma unroll
    for (int i = 0; i < 16; i++)
        #pragma unroll
        for (int j = 0; j < 4; j++) oacc[i][j] = 0.f;
    float sm0 = -1e30f, sm1 = -1e30f, l0 = 0.f, l1 = 0.f;

    const int row0 = qbase + qr0 + g;
    const int row1 = row0 + 8;

    const uint32_t aQB = sQ + (uint32_t)(((qr0 + (lane & 15)) * FQP + (lane >> 4) * 8) * 2);
    const uint32_t bRow = (uint32_t)((lane & 7) + ((lane >> 4) & 1) * 8);
    const uint32_t bCol = (uint32_t)(((lane >> 3) & 1) * 8);
    const uint32_t bKB = (uint32_t)((bRow * FQP + bCol) * 2);
    const uint32_t bVB = (uint32_t)((bRow * FVP + bCol) * 2);

    for (int kt = 0; kt <= ktmax; kt++) {
        const int st = kt & 1;
        if (kt < ktmax) {
            loadKV(st ^ 1, kt + 1);
            asm volatile("cp.async.wait_group 1;\n" ::: "memory");
        } else {
            asm volatile("cp.async.wait_group 0;\n" ::: "memory");
        }
        __syncthreads();

        const int kbase = kt * FBK;
        if (kbase <= qbase + qr0 + 15) {
            const uint32_t kSt = sK + (uint32_t)(st * FK_SZ) * 2u + bKB;
            const uint32_t vSt = sV + (uint32_t)(st * FV_SZ) * 2u + bVB;

            float sacc[8][4];
            #pragma unroll
            for (int nb = 0; nb < 8; nb++)
                #pragma unroll
                for (int j = 0; j < 4; j++) sacc[nb][j] = 0.f;

            #pragma unroll
            for (int kc = 0; kc < 12; kc++) {
                const uint32_t kby = (uint32_t)(kc * 32);
                uint32_t a[4];
                ldsm_x4(a[0], a[1], a[2], a[3], aQB + kby);
                uint32_t b[8][2];
                #pragma unroll
                for (int np = 0; np < 4; np++)
                    ldsm_x4(b[2*np][0], b[2*np][1], b[2*np+1][0], b[2*np+1][1],
                            kSt + (uint32_t)(np * 16 * FQP) * 2u + kby);
                #pragma unroll
                for (int nb = 0; nb < 8; nb++)
                    mma_f16(sacc[nb], a, b[nb]);
            }

            const bool need_mask = (kbase + FBK - 1) > (qbase + qr0);
            #pragma unroll
            for (int nb = 0; nb < 8; nb++) {
                const int c0 = kbase + nb * 8 + 2 * tig, c1 = c0 + 1;
                sacc[nb][0] *= scale; sacc[nb][1] *= scale;
                sacc[nb][2] *= scale; sacc[nb][3] *= scale;
                if (need_mask) {
                    if (c0 > row0) sacc[nb][0] = -1e30f;
                    if (c1 > row0) sacc[nb][1] = -1e30f;
                    if (c0 > row1) sacc[nb][2] = -1e30f;
                    if (c1 > row1) sacc[nb][3] = -1e30f;
                }
            }

            float mx0 = -1e30f, mx1 = -1e30f;
            #pragma unroll
            for (int nb = 0; nb < 8; nb++) {
                mx0 = fmaxf(mx0, fmaxf(sacc[nb][0], sacc[nb][1]));
                mx1 = fmaxf(mx1, fmaxf(sacc[nb][2], sacc[nb][3]));
            }
            mx0 = fmaxf(mx0, __shfl_xor_sync(0xFFFFFFFFu, mx0, 1));
            mx0 = fmaxf(mx0, __shfl_xor_sync(0xFFFFFFFFu, mx0, 2));
            mx1 = fmaxf(mx1, __shfl_xor_sync(0xFFFFFFFFu, mx1, 1));
            mx1 = fmaxf(mx1, __shfl_xor_sync(0xFFFFFFFFu, mx1, 2));

            const float mn0 = fmaxf(sm0, mx0), mn1 = fmaxf(sm1, mx1);
            const float al0 = __expf(sm0 - mn0), al1 = __expf(sm1 - mn1);
            sm0 = mn0; sm1 = mn1;

            uint32_t pA[8], pB[8];
            float ps0 = 0.f, ps1 = 0.f;
            #pragma unroll
            for (int nb = 0; nb < 8; nb++) {
                const float e0 = __expf(sacc[nb][0] - mn0);
                const float e1 = __expf(sacc[nb][1] - mn0);
                const float e2 = __expf(sacc[nb][2] - mn1);
                const float e3 = __expf(sacc[nb][3] - mn1);
                ps0 += e0 + e1; ps1 += e2 + e3;
                pA[nb] = h2u(__floats2half2_rn(e0, e1));
                pB[nb] = h2u(__floats2half2_rn(e2, e3));
            }
            l0 = l0 * al0 + ps0;
            l1 = l1 * al1 + ps1;

            #pragma unroll
            for (int nb2 = 0; nb2 < 16; nb2++) {
                oacc[nb2][0] *= al0; oacc[nb2][1] *= al0;
                oacc[nb2][2] *= al1; oacc[nb2][3] *= al1;
            }

            #pragma unroll
            for (int kc = 0; kc < 4; kc++) {
                uint32_t a[4] = { pA[2*kc], pB[2*kc], pA[2*kc+1], pB[2*kc+1] };
                const uint32_t kby = (uint32_t)(kc * 32);
                uint32_t bv[16][2];
                #pragma unroll
                for (int np = 0; np < 8; np++)
                    ldsm_x4(bv[2*np][0], bv[2*np][1], bv[2*np+1][0], bv[2*np+1][1],
                            vSt + (uint32_t)(np * 16 * FVP) * 2u + kby);
                #pragma unroll
                for (int nb2 = 0; nb2 < 16; nb2++)
                    mma_f16(oacc[nb2], a, bv[nb2]);
            }
        }
        __syncthreads();
    }

    l0 += __shfl_xor_sync(0xFFFFFFFFu, l0, 1);
    l0 += __shfl_xor_sync(0xFFFFFFFFu, l0, 2);
    l1 += __shfl_xor_sync(0xFFFFFFFFu, l1, 1);
    l1 += __shfl_xor_sync(0xFFFFFFFFu, l1, 2);
    const float inv0 = 1.f / l0, inv1 = 1.f / l1;

    const int b = bh / H_, h = bh % H_;
    __half* out0 = g_ctxh + (size_t)(b * S_ + row0) * (H_*VHD_) + h * VHD_;
    __half* out1 = out0 + (size_t)8 * (H_*VHD_);
    #pragma unroll
    for (int nb2 = 0; nb2 < 16; nb2++) {
        const int d = nb2 * 8 + 2 * tig;
        *(__half2*)(out0 + d) = __floats2half2_rn(oacc[nb2][0] * inv0, oacc[nb2][1] * inv0);
        *(__half2*)(out1 + d) = __floats2half2_rn(oacc[nb2][2] * inv1, oacc[nb2][3] * inv1);
    }
}

// ---------------- converts ----------------
__global__ void cvt_h(const float* __restrict__ src, __half* __restrict__ dst, int n4) {
    int i = blockIdx.x * blockDim.x + threadIdx.x;
    if (i >= n4) return;
    float4 v = ((const float4*)src)[i];
    ((__half2*)dst)[2*i]   = __floats2half2_rn(v.x, v.y);
    ((__half2*)dst)[2*i+1] = __floats2half2_rn(v.z, v.w);
}

__global__ void transpose_h(const float* __restrict__ src, __half* __restrict__ dst,
                            int K, int N, int Npad)
{
    __shared__ float tile[32][33];
    const int k0 = blockIdx.y * 32, n0 = blockIdx.x * 32;
    const int tx = threadIdx.x, ty = threadIdx.y;
    #pragma unroll
    for (int i = ty; i < 32; i += 8) {
        int k = k0 + i, n = n0 + tx;
        tile[i][tx] = (k < K && n < N) ? src[(size_t)k * N + n] : 0.f;
    }
    __syncthreads();
    #pragma unroll
    for (int i = ty; i < 32; i += 8) {
        int n = n0 + i, k = k0 + tx;
        if (n < Npad && k < K) dst[(size_t)n * K + k] = __float2half(tile[tx][i]);
    }
}

// ---------------- fused rmsnorm ----------------
__device__ __forceinline__ float block_reduce_sum(float v, float* sbuf) {
    int tid = threadIdx.x;
    sbuf[tid] = v; __syncthreads();
    #pragma unroll
    for (int s = 128; s > 0; s >>= 1) {
        if (tid < s) sbuf[tid] = sbuf[tid] + sbuf[tid + s];
        __syncthreads();
    }
    float r = sbuf[0]; __syncthreads();
    return r;
}

__global__ __launch_bounds__(256) void rms_both(const float* __restrict__ q_ln,
                                                const float* __restrict__ kv_ln)
{
    __shared__ float sbuf[256];
    const int row = blockIdx.x;
    const float* xr;
    const float* w;
    __half* yr;
    int n;
    if (row < TOK_) {
        xr = g_qa + (size_t)row * QR_; w = q_ln; yr = g_qah + (size_t)row * QR_; n = QR_;
    } else {
        int r = row - TOK_;
        xr = g_kvc + (size_t)r * KVO_; w = kv_ln; yr = g_kvnh + (size_t)r * KVR_; n = KVR_;
    }
    float acc = 0.f;
    for (int j = threadIdx.x; j < n; j += 256) { float v = xr[j]; acc += v * v; }
    float tot = block_reduce_sum(acc, sbuf);
    float scale = rsqrtf(tot / (float)n + EPS_);
    for (int j = threadIdx.x; j < n; j += 256) yr[j] = __float2half(xr[j] * scale * w[j]);
}

// ---------------- RoPE table + K-rope broadcast ----------------
__global__ void build_cs(const int* __restrict__ pos) {
    int idx = blockIdx.x * blockDim.x + threadIdx.x;
    if (idx >= TOK_ * 32) return;
    int j = idx & 31, tok = idx >> 5;
    float inv = powf(10000.f, -((float)(2 * j)) / 64.f);
    float ang = (float)pos[tok] * inv;
    g_cos[idx] = cosf(ang);
    g_sin[idx] = sinf(ang);
}

__global__ void rope_k() {
    int idx = blockIdx.x * blockDim.x + threadIdx.x;
    if (idx >= BH_ * S_ * 32) return;
    int j  = idx & 31;
    int r  = idx >> 5;
    int s  = r % S_;
    int bh = r / S_;
    int b  = bh / H_;
    int tok = b * S_ + s;
    const float* pb = g_kvc + (size_t)tok * KVO_ + KVR_;
    float c = g_cos[tok * 32 + j], sn = g_sin[tok * 32 + j];
    float ev = pb[2*j], ov = pb[2*j + 1];
    *(__half2*)&g_Kfh[((size_t)bh * S_ + s) * QKD_ + NOPE_ + 2*j] =
        __floats2half2_rn(ev * c - ov * sn, ov * c + ev * sn);
}

// ---------------- launcher ----------------
extern "C" void kernel_launch(void* const* d_in, const int* in_sizes, int n_in,
                              void* d_out, int out_size)
{
    const float* hs    = (const float*)d_in[0];
    const float* Wq_a  = (const float*)d_in[1];
    const float* q_ln  = (const float*)d_in[2];
    const float* Wq_b  = (const float*)d_in[3];
    const float* Wkv_a = (const float*)d_in[4];
    const float* kv_ln = (const float*)d_in[5];
    const float* Wkv_b = (const float*)d_in[6];
    const float* Wo    = (const float*)d_in[7];
    const int*   pos   = (const int*)  d_in[8];
    float* out = (float*)d_out;

    float *p_qa, *p_kvc;
    __half *p_qah, *p_kvnh, *p_Qfh, *p_ctxh;
    __half *p_hsch, *p_wqkvh, *p_wqbh, *p_wkvbh, *p_woh;
    cudaGetSymbolAddress((void**)&p_qa,    g_qa);
    cudaGetSymbolAddress((void**)&p_qah,   g_qah);
    cudaGetSymbolAddress((void**)&p_kvc,   g_kvc);
    cudaGetSymbolAddress((void**)&p_kvnh,  g_kvnh);
    cudaGetSymbolAddress((void**)&p_Qfh,   g_Qfh);
    cudaGetSymbolAddress((void**)&p_ctxh,  g_ctxh);
    cudaGetSymbolAddress((void**)&p_hsch,  g_hsch);
    cudaGetSymbolAddress((void**)&p_wqkvh, g_wqkvh);
    cudaGetSymbolAddress((void**)&p_wqbh,  g_wqbh);
    cudaGetSymbolAddress((void**)&p_wkvbh, g_wkvbh);
    cudaGetSymbolAddress((void**)&p_woh,   g_woh);

    static bool attr_done = false;
    if (!attr_done) {
        cudaFuncSetAttribute(hgemm<0>, cudaFuncAttributeMaxDynamicSharedMemorySize, SMEM_H);
        cudaFuncSetAttribute(hgemm<2>, cudaFuncAttributeMaxDynamicSharedMemorySize, SMEM_H);
        cudaFuncSetAttribute(hgemm<3>, cudaFuncAttributeMaxDynamicSharedMemorySize, SMEM_H);
        cudaFuncSetAttribute(hgemm<4>, cudaFuncAttributeMaxDynamicSharedMemorySize, SMEM_H);
        cudaFuncSetAttribute(flash_attn, cudaFuncAttributeMaxDynamicSharedMemorySize, FSMEM);
        attr_done = true;
    }

    // converts
    cvt_h<<<(TOK_*IN_/4 + 255)/256, 256>>>(hs, p_hsch, TOK_*IN_/4);
    dim3 tb(32, 8);
    transpose_h<<<dim3(QR_/32, IN_/32), tb>>>(Wq_a, p_wqkvh, IN_, QR_, QR_);
    transpose_h<<<dim3((KVO_+31)/32, IN_/32), tb>>>(Wkv_a, p_wqkvh + (size_t)QR_*IN_,
                                                    IN_, KVO_, KVO_);
    transpose_h<<<dim3((H_*QKD_)/32, QR_/32), tb>>>(Wq_b, p_wqbh, QR_, H_*QKD_, H_*QKD_);
    transpose_h<<<dim3((H_*(NOPE_+VHD_))/32, KVR_/32), tb>>>(Wkv_b, p_wkvbh,
                                                             KVR_, H_*(NOPE_+VHD_), H_*(NOPE_+VHD_));
    transpose_h<<<dim3(HID_/32, HID_/32), tb>>>(Wo, p_woh, HID_, HID_, HID_);
    build_cs<<<(TOK_*32 + 255)/256, 256>>>(pos);

    // merged qa + kva projection
    hgemm<2><<<dim3(NQKVP_/128, TOK_/128), 256, SMEM_H>>>(
        p_hsch, p_wqkvh, p_qa, nullptr, p_kvc, KVO_, QR_,
        TOK_, NQKV_, IN_, IN_, IN_, QR_);

    rms_both<<<2*TOK_, 256>>>(q_ln, kv_ln);
    rope_k<<<(BH_*S_*32 + 255)/256, 256>>>();

    // qb projection with fused RoPE + layout (writes g_Qfh)
    hgemm<3><<<dim3((H_*QKD_)/128, TOK_/128), 256, SMEM_H>>>(
        p_qah, p_wqbh, nullptr, p_Qfh, nullptr, 0, 0,
        TOK_, H_*QKD_, QR_, QR_, QR_, H_*QKD_);

    // kvb projection with fused K/V scatter
    hgemm<4><<<dim3((H_*(NOPE_+VHD_))/128, TOK_/128), 256, SMEM_H>>>(
        p_kvnh, p_wkvbh, nullptr, nullptr, nullptr, 0, 0,
        TOK_, H_*(NOPE_+VHD_), KVR_, KVR_, KVR_, H_*(NOPE_+VHD_));

    // fused attention
    float scale = 1.f / sqrtf((float)QKD_);
    flash_attn<<<dim3(S_/FBQ, BH_), 256, FSMEM>>>(scale);

    // output projection
    hgemm<0><<<dim3(HID_/128, TOK_/128), 256, SMEM_H>>>(
        p_ctxh, p_woh, out, nullptr, nullptr, 0, 0,
        TOK_, HID_, HID_, HID_, HID_, HID_);
}

// round 15
// speedup vs baseline: 1.0737x; 1.0405x over previous
#include <cuda_runtime.h>
#include <cuda_fp16.h>
#include <math.h>
#include <stdint.h>

// ---------------- problem constants ----------------
#define B_    2
#define S_    2048
#define HID_  2048
#define IN_   4096
#define H_    16
#define NOPE_ 128
#define ROPE_ 64
#define VHD_  128
#define QKD_  192
#define QR_   1536
#define KVR_  512
#define TOK_  (B_*S_)
#define BH_   (B_*H_)
#define EPS_  1e-6f
#define KVO_  (KVR_+ROPE_)   // 576
#define NQKV_ (QR_+KVO_)     // 2112
#define NQKVP_ 2176

// ---------------- scratch ----------------
__device__ float  g_qa  [TOK_*QR_];
__device__ __half g_qah [TOK_*QR_];
__device__ float  g_kvc [TOK_*KVO_];
__device__ __half g_kvnh[TOK_*KVR_];
__device__ __half g_Qfh [BH_*S_*QKD_];
__device__ __half g_Kfh [BH_*S_*QKD_];
__device__ __half g_Vth [BH_*VHD_*S_];             // V^T [bh][d][s]
__device__ __half g_ctxh[TOK_*(H_*VHD_)];
__device__ float  g_cos [TOK_*32];
__device__ float  g_sin [TOK_*32];
__device__ __half g_hsch  [TOK_*IN_];
__device__ __half g_wqkvh [NQKVP_*IN_];
__device__ __half g_wqbh  [(H_*QKD_)*QR_];
__device__ __half g_wkvbh [(H_*(NOPE_+VHD_))*KVR_];
__device__ __half g_woh   [HID_*HID_];

// ---------------- helpers ----------------
__device__ __forceinline__ void mma_f16(float c[4], const uint32_t a[4], const uint32_t b[2]) {
    asm volatile(
        "mma.sync.aligned.m16n8k16.row.col.f32.f16.f16.f32 "
        "{%0,%1,%2,%3}, {%4,%5,%6,%7}, {%8,%9}, {%0,%1,%2,%3};"
        : "+f"(c[0]), "+f"(c[1]), "+f"(c[2]), "+f"(c[3])
        : "r"(a[0]), "r"(a[1]), "r"(a[2]), "r"(a[3]), "r"(b[0]), "r"(b[1]));
}
__device__ __forceinline__ void ldsm_x4(uint32_t& r0, uint32_t& r1, uint32_t& r2, uint32_t& r3,
                                        uint32_t addr) {
    asm volatile("ldmatrix.sync.aligned.m8n8.x4.shared.b16 {%0,%1,%2,%3}, [%4];"
                 : "=r"(r0), "=r"(r1), "=r"(r2), "=r"(r3) : "r"(addr));
}
__device__ __forceinline__ void cp16(uint32_t dst, const void* src) {
    asm volatile("cp.async.cg.shared.global [%0], [%1], 16;\n" :: "r"(dst), "l"(src));
}
__device__ __forceinline__ void cp_commit() {
    asm volatile("cp.async.commit_group;\n" ::: "memory");
}
__device__ __forceinline__ uint32_t h2u(__half2 h) { return *(uint32_t*)&h; }

// ---------------- dense fp16 TB GEMM (R12 shape: 8 warps of 64x32, BK=32, 4 stages) ----------------
// MODE 0: fp32 out
// MODE 2: split fp32 out (cols < nsplit -> C, rest -> C2)
// MODE 3: qb epilogue — RoPE + [bh][s][QKD] half layout into Ch(=g_Qfh)
// MODE 4: kvb epilogue — K_nope -> g_Kfh, V -> g_Vth (transposed)
#define HBK 32
#define HP  40
#define H_STG (128*HP)
#define HSTG  4
#define SMEM_H (HSTG * 2 * H_STG * 2)

template<int MODE>
__global__ __launch_bounds__(256, 2) void hgemm(
    const __half* __restrict__ A, const __half* __restrict__ B,
    float* __restrict__ C, __half* __restrict__ Ch,
    float* __restrict__ C2, int ldc2, int nsplit,
    int M, int N, int K, int lda, int ldb, int ldc)
{
    extern __shared__ __half hsm[];
    __half* Asm = hsm;
    __half* Bsm = hsm + HSTG * H_STG;
    const uint32_t sA32 = (uint32_t)__cvta_generic_to_shared(Asm);
    const uint32_t sB32 = (uint32_t)__cvta_generic_to_shared(Bsm);

    const int nt = K / HBK;
    const int tid  = threadIdx.x;
    const int lane = tid & 31;
    const int g    = lane >> 2;
    const int tig  = lane & 3;
    const int wid  = tid >> 5;
    const int wm   = wid & 1;
    const int wn   = wid >> 1;
    const int rowBase = blockIdx.y * 128;
    const int colBase = blockIdx.x * 128;

    const int r  = tid >> 1;
    const int co = (tid & 1) << 4;
    const __half* Ap = A + (size_t)(rowBase + r) * lda + co;
    const __half* Bp = B + (size_t)(colBase + r) * ldb + co;
    const uint32_t a_dst = sA32 + (uint32_t)(r * HP + co) * 2u;
    const uint32_t b_dst = sB32 + (uint32_t)(r * HP + co) * 2u;

    auto load_stage = [&](int st, int kc) {
        const uint32_t so = (uint32_t)(st * H_STG) * 2u;
        const __half* as = Ap + kc * HBK;
        const __half* bs = Bp + kc * HBK;
        cp16(a_dst + so,      as);
        cp16(a_dst + so + 16, as + 8);
        cp16(b_dst + so,      bs);
        cp16(b_dst + so + 16, bs + 8);
        cp_commit();
    };

    const uint32_t aLB = (uint32_t)(((wm * 64 + (lane & 15)) * HP + (lane >> 4) * 8) * 2);
    const uint32_t bLB = (uint32_t)(((wn * 32 + (lane & 7) + ((lane >> 4) & 1) * 8) * HP
                                     + ((lane >> 3) & 1) * 8) * 2);

    float acc[4][4][4];
    #pragma unroll
    for (int i = 0; i < 4; i++)
        #pragma unroll
        for (int j = 0; j < 4; j++)
            #pragma unroll
            for (int q = 0; q < 4; q++) acc[i][j][q] = 0.f;

    #pragma unroll
    for (int s = 0; s < HSTG - 1; s++) {
        if (s < nt) load_stage(s, s);
        else        cp_commit();
    }

    for (int t = 0; t < nt; t++) {
        asm volatile("cp.async.wait_group 2;\n" ::: "memory");
        __syncthreads();

        const int tn = t + HSTG - 1;
        if (tn < nt) load_stage(tn % HSTG, tn);
        else         cp_commit();

        const uint32_t stoff = (uint32_t)((t % HSTG) * H_STG) * 2u;
        const uint32_t aSt = sA32 + stoff + aLB;
        const uint32_t bSt = sB32 + stoff + bLB;

        #pragma unroll
        for (int ks = 0; ks < 2; ks++) {
            const uint32_t kby = (uint32_t)(ks * 32);
            uint32_t afr[4][4], bfr[4][2];
            #pragma unroll
            for (int fm = 0; fm < 4; fm++)
                ldsm_x4(afr[fm][0], afr[fm][1], afr[fm][2], afr[fm][3],
                        aSt + (uint32_t)(fm * 16 * HP) * 2u + kby);
            #pragma unroll
            for (int fp = 0; fp < 2; fp++)
                ldsm_x4(bfr[2*fp][0], bfr[2*fp][1], bfr[2*fp+1][0], bfr[2*fp+1][1],
                        bSt + (uint32_t)(fp * 16 * HP) * 2u + kby);
            #pragma unroll
            for (int fm = 0; fm < 4; fm++)
                #pragma unroll
                for (int fn = 0; fn < 4; fn++)
                    mma_f16(acc[fm][fn], afr[fm], bfr[fn]);
        }
    }

    #pragma unroll
    for (int fm = 0; fm < 4; fm++) {
        #pragma unroll
        for (int fn = 0; fn < 4; fn++) {
            const int row = rowBase + wm * 64 + fm * 16 + g;
            const int col = colBase + wn * 32 + fn * 8 + tig * 2;   // always even
            if (col >= N) continue;
            const float a0 = acc[fm][fn][0], a1 = acc[fm][fn][1];
            const float a2 = acc[fm][fn][2], a3 = acc[fm][fn][3];

            if (MODE == 0) {
                *(float2*)&C[(size_t)row * ldc + col]       = make_float2(a0, a1);
                *(float2*)&C[(size_t)(row + 8) * ldc + col] = make_float2(a2, a3);
            } else if (MODE == 2) {
                if (col < nsplit) {
                    *(float2*)&C[(size_t)row * ldc + col]       = make_float2(a0, a1);
                    *(float2*)&C[(size_t)(row + 8) * ldc + col] = make_float2(a2, a3);
                } else {
                    const int c2 = col - nsplit;
                    *(float2*)&C2[(size_t)row * ldc2 + c2]       = make_float2(a0, a1);
                    *(float2*)&C2[(size_t)(row + 8) * ldc2 + c2] = make_float2(a2, a3);
                }
            } else if (MODE == 3) {
                const int h = col / QKD_, d = col - h * QKD_;
                #pragma unroll
                for (int rr = 0; rr < 2; rr++) {
                    const int tok = row + rr * 8;
                    const int b = tok >> 11, s = tok & (S_-1);
                    __half* dst = Ch + (((size_t)(b * H_ + h) * S_ + s) * QKD_ + d);
                    const float e = rr ? a2 : a0, o = rr ? a3 : a1;
                    __half2 hv;
                    if (d < NOPE_) {
                        hv = __floats2half2_rn(e, o);
                    } else {
                        const int j = (d - NOPE_) >> 1;
                        const float cc = g_cos[tok * 32 + j], ss = g_sin[tok * 32 + j];
                        hv = __floats2half2_rn(e * cc - o * ss, o * cc + e * ss);
                    }
                    *(__half2*)dst = hv;
                }
            } else {  // MODE 4
                const int h = col >> 8, d = col & 255;
                #pragma unroll
                for (int rr = 0; rr < 2; rr++) {
                    const int tok = row + rr * 8;
                    const int b = tok >> 11, s = tok & (S_-1);
                    const int bh = b * H_ + h;
                    const float e = rr ? a2 : a0, o = rr ? a3 : a1;
                    if (d < NOPE_) {
                        *(__half2*)&g_Kfh[((size_t)bh * S_ + s) * QKD_ + d] =
                            __floats2half2_rn(e, o);
                    } else {
                        const int dd = d - NOPE_;
                        __half* vb = g_Vth + ((size_t)bh * VHD_ + dd) * S_ + s;
                        vb[0]  = __float2half(e);
                        vb[S_] = __float2half(o);
                    }
                }
            }
        }
    }
}

// ---------------- fused flash attention: FBQ=64, 128 threads, 2 CTAs/SM ----------------
#define FBQ 64
#define FBK 64
#define FQP 200
#define FVP 72
#define FQ_SZ (FBQ*FQP)          // 12800 halves
#define FK_SZ (FBK*FQP)          // 12800 halves
#define FV_SZ (VHD_*FVP)         // 9216 halves (64 s-cols + pad per d-row)
#define FSMEM ((FQ_SZ + 2*FK_SZ + 2*FV_SZ) * 2)   // 113664 B

__global__ __launch_bounds__(128, 2) void flash_attn(float scale)
{
    extern __shared__ __half fsm[];
    __half* Qs  = fsm;
    __half* Ks0 = Qs + FQ_SZ;
    __half* Vs0 = Ks0 + 2 * FK_SZ;
    const uint32_t sQ = (uint32_t)__cvta_generic_to_shared(Qs);
    const uint32_t sK = (uint32_t)__cvta_generic_to_shared(Ks0);
    const uint32_t sV = (uint32_t)__cvta_generic_to_shared(Vs0);

    const int qt = (int)(gridDim.x - 1 - blockIdx.x);   // heavy tiles first
    const int bh = blockIdx.y;
    const int qbase = qt * FBQ;
    const int tid = threadIdx.x;
    const int wid = tid >> 5, lane = tid & 31, g = lane >> 2, tig = lane & 3;
    const int qr0 = wid * 16;                          // 4 warps x 16 rows

    const __half* Qg = g_Qfh + ((size_t)bh * S_ + qbase) * QKD_;
    const __half* Kg = g_Kfh + (size_t)bh * S_ * QKD_;
    const __half* Vg = g_Vth + (size_t)bh * VHD_ * S_;

    // Q tile: 64 rows, 2 threads/row, 96 halves each = 12 cp16
    {
        int r = tid >> 1, off = (tid & 1) * 96;
        const __half* src = Qg + (size_t)r * QKD_ + off;
        uint32_t dst = sQ + (uint32_t)(r * FQP + off) * 2u;
        #pragma unroll
        for (int c = 0; c < 12; c++) cp16(dst + c * 16, src + c * 8);
    }
    auto loadKV = [&](int st, int kt) {
        const int kbase = kt * FBK;
        // K: 64 rows, 2 threads/row, 96 halves each = 12 cp16
        {   int r = tid >> 1, off = (tid & 1) * 96;
            const __half* src = Kg + (size_t)(kbase + r) * QKD_ + off;
            uint32_t dst = sK + (uint32_t)(st * FK_SZ + r * FQP + off) * 2u;
            #pragma unroll
            for (int c = 0; c < 12; c++) cp16(dst + c * 16, src + c * 8);
        }
        // V: 128 d-rows, 1 thread/row, 64 halves = 8 cp16
        {   const __half* src = Vg + (size_t)tid * S_ + kbase;
            uint32_t dst = sV + (uint32_t)(st * FV_SZ + tid * FVP) * 2u;
            #pragma unroll
            for (int c = 0; c < 8; c++) cp16(dst + c * 16, src + c * 8);
        }
        cp_commit();
    };

    const int ktmax = (qbase + FBQ - 1) / FBK;
    loadKV(0, 0);

    float oacc[16][4];
    #pragma unroll
    for (int i = 0; i < 16; i++)
        #pragma unroll
        for (int j = 0; j < 4; j++) oacc[i][j] = 0.f;
    float sm0 = -1e30f, sm1 = -1e30f, l0 = 0.f, l1 = 0.f;

    const int row0 = qbase + qr0 + g;
    const int row1 = row0 + 8;

    const uint32_t aQB = sQ + (uint32_t)(((qr0 + (lane & 15)) * FQP + (lane >> 4) * 8) * 2);
    const uint32_t bRow = (uint32_t)((lane & 7) + ((lane >> 4) & 1) * 8);
    const uint32_t bCol = (uint32_t)(((lane >> 3) & 1) * 8);
    const uint32_t bKB = (uint32_t)((bRow * FQP + bCol) * 2);
    const uint32_t bVB = (uint32_t)((bRow * FVP + bCol) * 2);

    for (int kt = 0; kt <= ktmax; kt++) {
        const int st = kt & 1;
        if (kt < ktmax) {
            loadKV(st ^ 1, kt + 1);
            asm volatile("cp.async.wait_group 1;\n" ::: "memory");
        } else {
            asm volatile("cp.async.wait_group 0;\n" ::: "memory");
        }
        __syncthreads();

        const int kbase = kt * FBK;
        if (kbase <= qbase + qr0 + 15) {
            const uint32_t kSt = sK + (uint32_t)(st * FK_SZ) * 2u + bKB;
            const uint32_t vSt = sV + (uint32_t)(st * FV_SZ) * 2u + bVB;

            float sacc[8][4];
            #pragma unroll
            for (int nb = 0; nb < 8; nb++)
                #pragma unroll
                for (int j = 0; j < 4; j++) sacc[nb][j] = 0.f;

            #pragma unroll
            for (int kc = 0; kc < 12; kc++) {
                const uint32_t kby = (uint32_t)(kc * 32);
                uint32_t a[4];
                ldsm_x4(a[0], a[1], a[2], a[3], aQB + kby);
                uint32_t b[8][2];
                #pragma unroll
                for (int np = 0; np < 4; np++)
                    ldsm_x4(b[2*np][0], b[2*np][1], b[2*np+1][0], b[2*np+1][1],
                            kSt + (uint32_t)(np * 16 * FQP) * 2u + kby);
                #pragma unroll
                for (int nb = 0; nb < 8; nb++)
                    mma_f16(sacc[nb], a, b[nb]);
            }

            const bool need_mask = (kbase + FBK - 1) > (qbase + qr0);
            #pragma unroll
            for (int nb = 0; nb < 8; nb++) {
                const int c0 = kbase + nb * 8 + 2 * tig, c1 = c0 + 1;
                sacc[nb][0] *= scale; sacc[nb][1] *= scale;
                sacc[nb][2] *= scale; sacc[nb][3] *= scale;
                if (need_mask) {
                    if (c0 > row0) sacc[nb][0] = -1e30f;
                    if (c1 > row0) sacc[nb][1] = -1e30f;
                    if (c0 > row1) sacc[nb][2] = -1e30f;
                    if (c1 > row1) sacc[nb][3] = -1e30f;
                }
            }

            float mx0 = -1e30f, mx1 = -1e30f;
            #pragma unroll
            for (int nb = 0; nb < 8; nb++) {
                mx0 = fmaxf(mx0, fmaxf(sacc[nb][0], sacc[nb][1]));
                mx1 = fmaxf(mx1, fmaxf(sacc[nb][2], sacc[nb][3]));
            }
            mx0 = fmaxf(mx0, __shfl_xor_sync(0xFFFFFFFFu, mx0, 1));
            mx0 = fmaxf(mx0, __shfl_xor_sync(0xFFFFFFFFu, mx0, 2));
            mx1 = fmaxf(mx1, __shfl_xor_sync(0xFFFFFFFFu, mx1, 1));
            mx1 = fmaxf(mx1, __shfl_xor_sync(0xFFFFFFFFu, mx1, 2));

            const float mn0 = fmaxf(sm0, mx0), mn1 = fmaxf(sm1, mx1);
            const float al0 = __expf(sm0 - mn0), al1 = __expf(sm1 - mn1);
            sm0 = mn0; sm1 = mn1;

            uint32_t pA[8], pB[8];
            float ps0 = 0.f, ps1 = 0.f;
            #pragma unroll
            for (int nb = 0; nb < 8; nb++) {
                const float e0 = __expf(sacc[nb][0] - mn0);
                const float e1 = __expf(sacc[nb][1] - mn0);
                const float e2 = __expf(sacc[nb][2] - mn1);
                const float e3 = __expf(sacc[nb][3] - mn1);
                ps0 += e0 + e1; ps1 += e2 + e3;
                pA[nb] = h2u(__floats2half2_rn(e0, e1));
                pB[nb] = h2u(__floats2half2_rn(e2, e3));
            }
            l0 = l0 * al0 + ps0;
            l1 = l1 * al1 + ps1;

            #pragma unroll
            for (int nb2 = 0; nb2 < 16; nb2++) {
                oacc[nb2][0] *= al0; oacc[nb2][1] *= al0;
                oacc[nb2][2] *= al1; oacc[nb2][3] *= al1;
            }

            #pragma unroll
            for (int kc = 0; kc < 4; kc++) {
                uint32_t a[4] = { pA[2*kc], pB[2*kc], pA[2*kc+1], pB[2*kc+1] };
                const uint32_t kby = (uint32_t)(kc * 32);
                uint32_t bv[16][2];
                #pragma unroll
                for (int np = 0; np < 8; np++)
                    ldsm_x4(bv[2*np][0], bv[2*np][1], bv[2*np+1][0], bv[2*np+1][1],
                            vSt + (uint32_t)(np * 16 * FVP) * 2u + kby);
                #pragma unroll
                for (int nb2 = 0; nb2 < 16; nb2++)
                    mma_f16(oacc[nb2], a, bv[nb2]);
            }
        }
        __syncthreads();
    }

    l0 += __shfl_xor_sync(0xFFFFFFFFu, l0, 1);
    l0 += __shfl_xor_sync(0xFFFFFFFFu, l0, 2);
    l1 += __shfl_xor_sync(0xFFFFFFFFu, l1, 1);
    l1 += __shfl_xor_sync(0xFFFFFFFFu, l1, 2);
    const float inv0 = 1.f / l0, inv1 = 1.f / l1;

    const int b = bh / H_, h = bh % H_;
    __half* out0 = g_ctxh + (size_t)(b * S_ + row0) * (H_*VHD_) + h * VHD_;
    __half* out1 = out0 + (size_t)8 * (H_*VHD_);
    #pragma unroll
    for (int nb2 = 0; nb2 < 16; nb2++) {
        const int d = nb2 * 8 + 2 * tig;
        *(__half2*)(out0 + d) = __floats2half2_rn(oacc[nb2][0] * inv0, oacc[nb2][1] * inv0);
        *(__half2*)(out1 + d) = __floats2half2_rn(oacc[nb2][2] * inv1, oacc[nb2][3] * inv1);
    }
}

// ---------------- converts ----------------
__global__ void cvt_h(const float* __restrict__ src, __half* __restrict__ dst, int n4) {
    int i = blockIdx.x * blockDim.x + threadIdx.x;
    if (i >= n4) return;
    float4 v = ((const float4*)src)[i];
    ((__half2*)dst)[2*i]   = __floats2half2_rn(v.x, v.y);
    ((__half2*)dst)[2*i+1] = __floats2half2_rn(v.z, v.w);
}

__global__ void transpose_h(const float* __restrict__ src, __half* __restrict__ dst,
                            int K, int N, int Npad)
{
    __shared__ float tile[32][33];
    const int k0 = blockIdx.y * 32, n0 = blockIdx.x * 32;
    const int tx = threadIdx.x, ty = threadIdx.y;
    #pragma unroll
    for (int i = ty; i < 32; i += 8) {
        int k = k0 + i, n = n0 + tx;
        tile[i][tx] = (k < K && n < N) ? src[(size_t)k * N + n] : 0.f;
    }
    __syncthreads();
    #pragma unroll
    for (int i = ty; i < 32; i += 8) {
        int n = n0 + i, k = k0 + tx;
        if (n < Npad && k < K) dst[(size_t)n * K + k] = __float2half(tile[tx][i]);
    }
}

// ---------------- fused rmsnorm ----------------
__device__ __forceinline__ float block_reduce_sum(float v, float* sbuf) {
    int tid = threadIdx.x;
    sbuf[tid] = v; __syncthreads();
    #pragma unroll
    for (int s = 128; s > 0; s >>= 1) {
        if (tid < s) sbuf[tid] = sbuf[tid] + sbuf[tid + s];
        __syncthreads();
    }
    float r = sbuf[0]; __syncthreads();
    return r;
}

__global__ __launch_bounds__(256) void rms_both(const float* __restrict__ q_ln,
                                                const float* __restrict__ kv_ln)
{
    __shared__ float sbuf[256];
    const int row = blockIdx.x;
    const float* xr;
    const float* w;
    __half* yr;
    int n;
    if (row < TOK_) {
        xr = g_qa + (size_t)row * QR_; w = q_ln; yr = g_qah + (size_t)row * QR_; n = QR_;
    } else {
        int r = row - TOK_;
        xr = g_kvc + (size_t)r * KVO_; w = kv_ln; yr = g_kvnh + (size_t)r * KVR_; n = KVR_;
    }
    float acc = 0.f;
    for (int j = threadIdx.x; j < n; j += 256) { float v = xr[j]; acc += v * v; }
    float tot = block_reduce_sum(acc, sbuf);
    float scale = rsqrtf(tot / (float)n + EPS_);
    for (int j = threadIdx.x; j < n; j += 256) yr[j] = __float2half(xr[j] * scale * w[j]);
}

// ---------------- RoPE table + K-rope broadcast ----------------
__global__ void build_cs(const int* __restrict__ pos) {
    int idx = blockIdx.x * blockDim.x + threadIdx.x;
    if (idx >= TOK_ * 32) return;
    int j = idx & 31, tok = idx >> 5;
    float inv = powf(10000.f, -((float)(2 * j)) / 64.f);
    float ang = (float)pos[tok] * inv;
    g_cos[idx] = cosf(ang);
    g_sin[idx] = sinf(ang);
}

__global__ void rope_k() {
    int idx = blockIdx.x * blockDim.x + threadIdx.x;
    if (idx >= BH_ * S_ * 32) return;
    int j  = idx & 31;
    int r  = idx >> 5;
    int s  = r % S_;
    int bh = r / S_;
    int b  = bh / H_;
    int tok = b * S_ + s;
    const float* pb = g_kvc + (size_t)tok * KVO_ + KVR_;
    float c = g_cos[tok * 32 + j], sn = g_sin[tok * 32 + j];
    float ev = pb[2*j], ov = pb[2*j + 1];
    *(__half2*)&g_Kfh[((size_t)bh * S_ + s) * QKD_ + NOPE_ + 2*j] =
        __floats2half2_rn(ev * c - ov * sn, ov * c + ev * sn);
}

// ---------------- launcher ----------------
extern "C" void kernel_launch(void* const* d_in, const int* in_sizes, int n_in,
                              void* d_out, int out_size)
{
    const float* hs    = (const float*)d_in[0];
    const float* Wq_a  = (const float*)d_in[1];
    const float* q_ln  = (const float*)d_in[2];
    const float* Wq_b  = (const float*)d_in[3];
    const float* Wkv_a = (const float*)d_in[4];
    const float* kv_ln = (const float*)d_in[5];
    const float* Wkv_b = (const float*)d_in[6];
    const float* Wo    = (const float*)d_in[7];
    const int*   pos   = (const int*)  d_in[8];
    float* out = (float*)d_out;

    float *p_qa, *p_kvc;
    __half *p_qah, *p_kvnh, *p_Qfh, *p_ctxh;
    __half *p_hsch, *p_wqkvh, *p_wqbh, *p_wkvbh, *p_woh;
    cudaGetSymbolAddress((void**)&p_qa,    g_qa);
    cudaGetSymbolAddress((void**)&p_qah,   g_qah);
    cudaGetSymbolAddress((void**)&p_kvc,   g_kvc);
    cudaGetSymbolAddress((void**)&p_kvnh,  g_kvnh);
    cudaGetSymbolAddress((void**)&p_Qfh,   g_Qfh);
    cudaGetSymbolAddress((void**)&p_ctxh,  g_ctxh);
    cudaGetSymbolAddress((void**)&p_hsch,  g_hsch);
    cudaGetSymbolAddress((void**)&p_wqkvh, g_wqkvh);
    cudaGetSymbolAddress((void**)&p_wqbh,  g_wqbh);
    cudaGetSymbolAddress((void**)&p_wkvbh, g_wkvbh);
    cudaGetSymbolAddress((void**)&p_woh,   g_woh);

    static bool attr_done = false;
    if (!attr_done) {
        cudaFuncSetAttribute(hgemm<0>, cudaFuncAttributeMaxDynamicSharedMemorySize, SMEM_H);
        cudaFuncSetAttribute(hgemm<2>, cudaFuncAttributeMaxDynamicSharedMemorySize, SMEM_H);
        cudaFuncSetAttribute(hgemm<3>, cudaFuncAttributeMaxDynamicSharedMemorySize, SMEM_H);
        cudaFuncSetAttribute(hgemm<4>, cudaFuncAttributeMaxDynamicSharedMemorySize, SMEM_H);
        cudaFuncSetAttribute(flash_attn, cudaFuncAttributeMaxDynamicSharedMemorySize, FSMEM);
        attr_done = true;
    }

    // converts
    cvt_h<<<(TOK_*IN_/4 + 255)/256, 256>>>(hs, p_hsch, TOK_*IN_/4);
    dim3 tb(32, 8);
    transpose_h<<<dim3(QR_/32, IN_/32), tb>>>(Wq_a, p_wqkvh, IN_, QR_, QR_);
    transpose_h<<<dim3((KVO_+31)/32, IN_/32), tb>>>(Wkv_a, p_wqkvh + (size_t)QR_*IN_,
                                                    IN_, KVO_, KVO_);
    transpose_h<<<dim3((H_*QKD_)/32, QR_/32), tb>>>(Wq_b, p_wqbh, QR_, H_*QKD_, H_*QKD_);
    transpose_h<<<dim3((H_*(NOPE_+VHD_))/32, KVR_/32), tb>>>(Wkv_b, p_wkvbh,
                                                             KVR_, H_*(NOPE_+VHD_), H_*(NOPE_+VHD_));
    transpose_h<<<dim3(HID_/32, HID_/32), tb>>>(Wo, p_woh, HID_, HID_, HID_);
    build_cs<<<(TOK_*32 + 255)/256, 256>>>(pos);

    // merged qa + kva projection
    hgemm<2><<<dim3(NQKVP_/128, TOK_/128), 256, SMEM_H>>>(
        p_hsch, p_wqkvh, p_qa, nullptr, p_kvc, KVO_, QR_,
        TOK_, NQKV_, IN_, IN_, IN_, QR_);

    rms_both<<<2*TOK_, 256>>>(q_ln, kv_ln);
    rope_k<<<(BH_*S_*32 + 255)/256, 256>>>();

    // qb projection with fused RoPE + layout (writes g_Qfh)
    hgemm<3><<<dim3((H_*QKD_)/128, TOK_/128), 256, SMEM_H>>>(
        p_qah, p_wqbh, nullptr, p_Qfh, nullptr, 0, 0,
        TOK_, H_*QKD_, QR_, QR_, QR_, H_*QKD_);

    // kvb projection with fused K/V scatter
    hgemm<4><<<dim3((H_*(NOPE_+VHD_))/128, TOK_/128), 256, SMEM_H>>>(
        p_kvnh, p_wkvbh, nullptr, nullptr, nullptr, 0, 0,
        TOK_, H_*(NOPE_+VHD_), KVR_, KVR_, KVR_, H_*(NOPE_+VHD_));

    // fused attention (FBQ=64, 2 CTAs/SM)
    float scale = 1.f / sqrtf((float)QKD_);
    flash_attn<<<dim3(S_/FBQ, BH_), 128, FSMEM>>>(scale);

    // output projection
    hgemm<0><<<dim3(HID_/128, TOK_/128), 256, SMEM_H>>>(
        p_ctxh, p_woh, out, nullptr, nullptr, 0, 0,
        TOK_, HID_, HID_, HID_, HID_, HID_);
}

// round 16
// speedup vs baseline: 1.1427x; 1.0642x over previous
#include <cuda_runtime.h>
#include <cuda_fp16.h>
#include <math.h>
#include <stdint.h>

// ---------------- problem constants ----------------
#define B_    2
#define S_    2048
#define HID_  2048
#define IN_   4096
#define H_    16
#define NOPE_ 128
#define ROPE_ 64
#define VHD_  128
#define QKD_  192
#define QR_   1536
#define KVR_  512
#define TOK_  (B_*S_)
#define BH_   (B_*H_)
#define EPS_  1e-6f
#define KVO_  (KVR_+ROPE_)   // 576
#define NQKV_ (QR_+KVO_)     // 2112
#define NQKVP_ 2176
#define QB_COLS ((H_*QKD_)/128)          // 24

// ---------------- scratch ----------------
__device__ float  g_qa  [TOK_*QR_];
__device__ __half g_qah [TOK_*QR_];
__device__ float  g_kvc [TOK_*KVO_];
__device__ __half g_kvnh[TOK_*KVR_];
__device__ __half g_Qfh [BH_*S_*QKD_];
__device__ __half g_Kfh [BH_*S_*QKD_];
__device__ __half g_Vth [BH_*VHD_*S_];             // V^T [bh][d][s]
__device__ __half g_ctxh[TOK_*(H_*VHD_)];
__device__ float  g_cos [TOK_*32];
__device__ float  g_sin [TOK_*32];
__device__ __half g_hsch  [TOK_*IN_];
__device__ __half g_wqkvh [NQKVP_*IN_];
__device__ __half g_wqbh  [(H_*QKD_)*QR_];
__device__ __half g_wkvbh [(H_*(NOPE_+VHD_))*KVR_];
__device__ __half g_woh   [HID_*HID_];

// ---------------- helpers ----------------
__device__ __forceinline__ void mma_f16(float c[4], const uint32_t a[4], const uint32_t b[2]) {
    asm volatile(
        "mma.sync.aligned.m16n8k16.row.col.f32.f16.f16.f32 "
        "{%0,%1,%2,%3}, {%4,%5,%6,%7}, {%8,%9}, {%0,%1,%2,%3};"
        : "+f"(c[0]), "+f"(c[1]), "+f"(c[2]), "+f"(c[3])
        : "r"(a[0]), "r"(a[1]), "r"(a[2]), "r"(a[3]), "r"(b[0]), "r"(b[1]));
}
__device__ __forceinline__ void ldsm_x4(uint32_t& r0, uint32_t& r1, uint32_t& r2, uint32_t& r3,
                                        uint32_t addr) {
    asm volatile("ldmatrix.sync.aligned.m8n8.x4.shared.b16 {%0,%1,%2,%3}, [%4];"
                 : "=r"(r0), "=r"(r1), "=r"(r2), "=r"(r3) : "r"(addr));
}
__device__ __forceinline__ void cp16(uint32_t dst, const void* src) {
    asm volatile("cp.async.cg.shared.global [%0], [%1], 16;\n" :: "r"(dst), "l"(src));
}
__device__ __forceinline__ void cp_commit() {
    asm volatile("cp.async.commit_group;\n" ::: "memory");
}
__device__ __forceinline__ uint32_t h2u(__half2 h) { return *(uint32_t*)&h; }

// ---------------- dense fp16 TB GEMM (R12 shape: 8 warps of 64x32, BK=32, 4 stages) ----------------
#define HBK 32
#define HP  40
#define H_STG (128*HP)
#define HSTG  4
#define SMEM_H (HSTG * 2 * H_STG * 2)

// shared mainloop: fills acc[4][4][4] from A/B tiles
#define GEMM_MAINLOOP(Aptr, Bptr, Kdim, LDA, LDB)                                     \
    const int nt = (Kdim) / HBK;                                                      \
    const int r  = tid >> 1;                                                          \
    const int co = (tid & 1) << 4;                                                    \
    const __half* Ap = (Aptr) + (size_t)(rowBase + r) * (LDA) + co;                   \
    const __half* Bp = (Bptr) + (size_t)(colBase + r) * (LDB) + co;                   \
    const uint32_t a_dst = sA32 + (uint32_t)(r * HP + co) * 2u;                       \
    const uint32_t b_dst = sB32 + (uint32_t)(r * HP + co) * 2u;                       \
    auto load_stage = [&](int st, int kc) {                                           \
        const uint32_t so = (uint32_t)(st * H_STG) * 2u;                              \
        const __half* as = Ap + kc * HBK;                                             \
        const __half* bs = Bp + kc * HBK;                                             \
        cp16(a_dst + so,      as);                                                    \
        cp16(a_dst + so + 16, as + 8);                                                \
        cp16(b_dst + so,      bs);                                                    \
        cp16(b_dst + so + 16, bs + 8);                                                \
        cp_commit();                                                                  \
    };                                                                                \
    const uint32_t aLB = (uint32_t)(((wm * 64 + (lane & 15)) * HP + (lane >> 4) * 8) * 2); \
    const uint32_t bLB = (uint32_t)(((wn * 32 + (lane & 7) + ((lane >> 4) & 1) * 8) * HP   \
                                     + ((lane >> 3) & 1) * 8) * 2);                   \
    _Pragma("unroll")                                                                 \
    for (int s = 0; s < HSTG - 1; s++) {                                              \
        if (s < nt) load_stage(s, s);                                                 \
        else        cp_commit();                                                      \
    }                                                                                 \
    for (int t = 0; t < nt; t++) {                                                    \
        asm volatile("cp.async.wait_group 2;\n" ::: "memory");                        \
        __syncthreads();                                                              \
        const int tn = t + HSTG - 1;                                                  \
        if (tn < nt) load_stage(tn % HSTG, tn);                                       \
        else         cp_commit();                                                     \
        const uint32_t stoff = (uint32_t)((t % HSTG) * H_STG) * 2u;                   \
        const uint32_t aSt = sA32 + stoff + aLB;                                      \
        const uint32_t bSt = sB32 + stoff + bLB;                                      \
        _Pragma("unroll")                                                             \
        for (int ks = 0; ks < 2; ks++) {                                              \
            const uint32_t kby = (uint32_t)(ks * 32);                                 \
            uint32_t afr[4][4], bfr[4][2];                                            \
            _Pragma("unroll")                                                         \
            for (int fm = 0; fm < 4; fm++)                                            \
                ldsm_x4(afr[fm][0], afr[fm][1], afr[fm][2], afr[fm][3],               \
                        aSt + (uint32_t)(fm * 16 * HP) * 2u + kby);                   \
            _Pragma("unroll")                                                         \
            for (int fp = 0; fp < 2; fp++)                                            \
                ldsm_x4(bfr[2*fp][0], bfr[2*fp][1], bfr[2*fp+1][0], bfr[2*fp+1][1],   \
                        bSt + (uint32_t)(fp * 16 * HP) * 2u + kby);                   \
            _Pragma("unroll")                                                         \
            for (int fm = 0; fm < 4; fm++)                                            \
                _Pragma("unroll")                                                     \
                for (int fn = 0; fn < 4; fn++)                                        \
                    mma_f16(acc[fm][fn], afr[fm], bfr[fn]);                           \
        }                                                                             \
    }

// MODE 0: fp32 out; MODE 2: split fp32 out
template<int MODE>
__global__ __launch_bounds__(256, 2) void hgemm(
    const __half* __restrict__ A, const __half* __restrict__ B,
    float* __restrict__ C, float* __restrict__ C2, int ldc2, int nsplit,
    int M, int N, int K, int lda, int ldb, int ldc)
{
    extern __shared__ __half hsm[];
    const uint32_t sA32 = (uint32_t)__cvta_generic_to_shared(hsm);
    const uint32_t sB32 = (uint32_t)__cvta_generic_to_shared(hsm + HSTG * H_STG);

    const int tid  = threadIdx.x;
    const int lane = tid & 31;
    const int g    = lane >> 2;
    const int tig  = lane & 3;
    const int wid  = tid >> 5;
    const int wm   = wid & 1;
    const int wn   = wid >> 1;
    const int rowBase = blockIdx.y * 128;
    const int colBase = blockIdx.x * 128;

    float acc[4][4][4];
    #pragma unroll
    for (int i = 0; i < 4; i++)
        #pragma unroll
        for (int j = 0; j < 4; j++)
            #pragma unroll
            for (int q = 0; q < 4; q++) acc[i][j][q] = 0.f;

    GEMM_MAINLOOP(A, B, K, lda, ldb)

    #pragma unroll
    for (int fm = 0; fm < 4; fm++) {
        #pragma unroll
        for (int fn = 0; fn < 4; fn++) {
            const int row = rowBase + wm * 64 + fm * 16 + g;
            const int col = colBase + wn * 32 + fn * 8 + tig * 2;
            if (col >= N) continue;
            const float a0 = acc[fm][fn][0], a1 = acc[fm][fn][1];
            const float a2 = acc[fm][fn][2], a3 = acc[fm][fn][3];
            if (MODE == 0) {
                *(float2*)&C[(size_t)row * ldc + col]       = make_float2(a0, a1);
                *(float2*)&C[(size_t)(row + 8) * ldc + col] = make_float2(a2, a3);
            } else {
                if (col < nsplit) {
                    *(float2*)&C[(size_t)row * ldc + col]       = make_float2(a0, a1);
                    *(float2*)&C[(size_t)(row + 8) * ldc + col] = make_float2(a2, a3);
                } else {
                    const int c2 = col - nsplit;
                    *(float2*)&C2[(size_t)row * ldc2 + c2]       = make_float2(a0, a1);
                    *(float2*)&C2[(size_t)(row + 8) * ldc2 + c2] = make_float2(a2, a3);
                }
            }
        }
    }
}

// merged qb + kvb projections: blockIdx.x < QB_COLS -> qb (RoPE epilogue), else kvb (K/V scatter)
__global__ __launch_bounds__(256, 2) void hgemm_qkv()
{
    extern __shared__ __half hsm[];
    const uint32_t sA32 = (uint32_t)__cvta_generic_to_shared(hsm);
    const uint32_t sB32 = (uint32_t)__cvta_generic_to_shared(hsm + HSTG * H_STG);

    const int tid  = threadIdx.x;
    const int lane = tid & 31;
    const int g    = lane >> 2;
    const int tig  = lane & 3;
    const int wid  = tid >> 5;
    const int wm   = wid & 1;
    const int wn   = wid >> 1;
    const int rowBase = blockIdx.y * 128;
    const bool isq = (blockIdx.x < QB_COLS);
    const int colBase = (isq ? blockIdx.x : (blockIdx.x - QB_COLS)) * 128;

    float acc[4][4][4];
    #pragma unroll
    for (int i = 0; i < 4; i++)
        #pragma unroll
        for (int j = 0; j < 4; j++)
            #pragma unroll
            for (int q = 0; q < 4; q++) acc[i][j][q] = 0.f;

    {
        const __half* Asel = isq ? g_qah  : g_kvnh;
        const __half* Bsel = isq ? g_wqbh : g_wkvbh;
        const int Ksel = isq ? QR_ : KVR_;
        GEMM_MAINLOOP(Asel, Bsel, Ksel, Ksel, Ksel)
    }

    #pragma unroll
    for (int fm = 0; fm < 4; fm++) {
        #pragma unroll
        for (int fn = 0; fn < 4; fn++) {
            const int row = rowBase + wm * 64 + fm * 16 + g;
            const int col = colBase + wn * 32 + fn * 8 + tig * 2;   // even
            const float a0 = acc[fm][fn][0], a1 = acc[fm][fn][1];
            const float a2 = acc[fm][fn][2], a3 = acc[fm][fn][3];
            if (isq) {
                const int h = col / QKD_, d = col - h * QKD_;
                #pragma unroll
                for (int rr = 0; rr < 2; rr++) {
                    const int tok = row + rr * 8;
                    const int b = tok >> 11, s = tok & (S_-1);
                    __half* dst = g_Qfh + (((size_t)(b * H_ + h) * S_ + s) * QKD_ + d);
                    const float e = rr ? a2 : a0, o = rr ? a3 : a1;
                    __half2 hv;
                    if (d < NOPE_) {
                        hv = __floats2half2_rn(e, o);
                    } else {
                        const int j = (d - NOPE_) >> 1;
                        const float cc = g_cos[tok * 32 + j], ss = g_sin[tok * 32 + j];
                        hv = __floats2half2_rn(e * cc - o * ss, o * cc + e * ss);
                    }
                    *(__half2*)dst = hv;
                }
            } else {
                const int h = col >> 8, d = col & 255;
                #pragma unroll
                for (int rr = 0; rr < 2; rr++) {
                    const int tok = row + rr * 8;
                    const int b = tok >> 11, s = tok & (S_-1);
                    const int bh = b * H_ + h;
                    const float e = rr ? a2 : a0, o = rr ? a3 : a1;
                    if (d < NOPE_) {
                        *(__half2*)&g_Kfh[((size_t)bh * S_ + s) * QKD_ + d] =
                            __floats2half2_rn(e, o);
                    } else {
                        const int dd = d - NOPE_;
                        __half* vb = g_Vth + ((size_t)bh * VHD_ + dd) * S_ + s;
                        vb[0]  = __float2half(e);
                        vb[S_] = __float2half(o);
                    }
                }
            }
        }
    }
}

// ---------------- fused flash attention (R12: FBQ=128, 256 threads) ----------------
#define FBQ 128
#define FBK 64
#define FQP 200
#define FVP 72
#define FQ_SZ (FBQ*FQP)
#define FK_SZ (FBK*FQP)
#define FV_SZ (VHD_*FVP)
#define FSMEM ((FQ_SZ + 2*FK_SZ + 2*FV_SZ) * 2)

__global__ __launch_bounds__(256, 1) void flash_attn(float scale)
{
    extern __shared__ __half fsm[];
    __half* Qs  = fsm;
    __half* Ks0 = Qs + FQ_SZ;
    __half* Vs0 = Ks0 + 2 * FK_SZ;
    const uint32_t sQ = (uint32_t)__cvta_generic_to_shared(Qs);
    const uint32_t sK = (uint32_t)__cvta_generic_to_shared(Ks0);
    const uint32_t sV = (uint32_t)__cvta_generic_to_shared(Vs0);

    const int qt = (int)(gridDim.x - 1 - blockIdx.x);
    const int bh = blockIdx.y;
    const int qbase = qt * FBQ;
    const int tid = threadIdx.x;
    const int wid = tid >> 5, lane = tid & 31, g = lane >> 2, tig = lane & 3;
    const int qr0 = wid * 16;

    const __half* Qg = g_Qfh + ((size_t)bh * S_ + qbase) * QKD_;
    const __half* Kg = g_Kfh + (size_t)bh * S_ * QKD_;
    const __half* Vg = g_Vth + (size_t)bh * VHD_ * S_;

    {
        int r = tid >> 1, off = (tid & 1) * 96;
        const __half* src = Qg + (size_t)r * QKD_ + off;
        uint32_t dst = sQ + (uint32_t)(r * FQP + off) * 2u;
        #pragma unroll
        for (int c = 0; c < 12; c++) cp16(dst + c * 16, src + c * 8);
    }
    auto loadKV = [&](int st, int kt) {
        const int kbase = kt * FBK;
        {   int r = tid >> 2, off = (tid & 3) * 48;
            const __half* src = Kg + (size_t)(kbase + r) * QKD_ + off;
            uint32_t dst = sK + (uint32_t)(st * FK_SZ + r * FQP + off) * 2u;
            #pragma unroll
            for (int c = 0; c < 6; c++) cp16(dst + c * 16, src + c * 8);
        }
        {   int r = tid >> 1, off = (tid & 1) * 32;
            const __half* src = Vg + (size_t)r * S_ + kbase + off;
            uint32_t dst = sV + (uint32_t)(st * FV_SZ + r * FVP + off) * 2u;
            #pragma unroll
            for (int c = 0; c < 4; c++) cp16(dst + c * 16, src + c * 8);
        }
        cp_commit();
    };

    const int ktmax = (qbase + FBQ - 1) / FBK;
    loadKV(0, 0);

    float oacc[16][4];
    #pragma unroll
    for (int i = 0; i < 16; i++)
        #pragma unroll
        for (int j = 0; j < 4; j++) oacc[i][j] = 0.f;
    float sm0 = -1e30f, sm1 = -1e30f, l0 = 0.f, l1 = 0.f;

    const int row0 = qbase + qr0 + g;
    const int row1 = row0 + 8;

    const uint32_t aQB = sQ + (uint32_t)(((qr0 + (lane & 15)) * FQP + (lane >> 4) * 8) * 2);
    const uint32_t bRow = (uint32_t)((lane & 7) + ((lane >> 4) & 1) * 8);
    const uint32_t bCol = (uint32_t)(((lane >> 3) & 1) * 8);
    const uint32_t bKB = (uint32_t)((bRow * FQP + bCol) * 2);
    const uint32_t bVB = (uint32_t)((bRow * FVP + bCol) * 2);

    for (int kt = 0; kt <= ktmax; kt++) {
        const int st = kt & 1;
        if (kt < ktmax) {
            loadKV(st ^ 1, kt + 1);
            asm volatile("cp.async.wait_group 1;\n" ::: "memory");
        } else {
            asm volatile("cp.async.wait_group 0;\n" ::: "memory");
        }
        __syncthreads();

        const int kbase = kt * FBK;
        if (kbase <= qbase + qr0 + 15) {
            const uint32_t kSt = sK + (uint32_t)(st * FK_SZ) * 2u + bKB;
            const uint32_t vSt = sV + (uint32_t)(st * FV_SZ) * 2u + bVB;

            float sacc[8][4];
            #pragma unroll
            for (int nb = 0; nb < 8; nb++)
                #pragma unroll
                for (int j = 0; j < 4; j++) sacc[nb][j] = 0.f;

            #pragma unroll
            for (int kc = 0; kc < 12; kc++) {
                const uint32_t kby = (uint32_t)(kc * 32);
                uint32_t a[4];
                ldsm_x4(a[0], a[1], a[2], a[3], aQB + kby);
                uint32_t b[8][2];
                #pragma unroll
                for (int np = 0; np < 4; np++)
                    ldsm_x4(b[2*np][0], b[2*np][1], b[2*np+1][0], b[2*np+1][1],
                            kSt + (uint32_t)(np * 16 * FQP) * 2u + kby);
                #pragma unroll
                for (int nb = 0; nb < 8; nb++)
                    mma_f16(sacc[nb], a, b[nb]);
            }

            const bool need_mask = (kbase + FBK - 1) > (qbase + qr0);
            #pragma unroll
            for (int nb = 0; nb < 8; nb++) {
                const int c0 = kbase + nb * 8 + 2 * tig, c1 = c0 + 1;
                sacc[nb][0] *= scale; sacc[nb][1] *= scale;
                sacc[nb][2] *= scale; sacc[nb][3] *= scale;
                if (need_mask) {
                    if (c0 > row0) sacc[nb][0] = -1e30f;
                    if (c1 > row0) sacc[nb][1] = -1e30f;
                    if (c0 > row1) sacc[nb][2] = -1e30f;
                    if (c1 > row1) sacc[nb][3] = -1e30f;
                }
            }

            float mx0 = -1e30f, mx1 = -1e30f;
            #pragma unroll
            for (int nb = 0; nb < 8; nb++) {
                mx0 = fmaxf(mx0, fmaxf(sacc[nb][0], sacc[nb][1]));
                mx1 = fmaxf(mx1, fmaxf(sacc[nb][2], sacc[nb][3]));
            }
            mx0 = fmaxf(mx0, __shfl_xor_sync(0xFFFFFFFFu, mx0, 1));
            mx0 = fmaxf(mx0, __shfl_xor_sync(0xFFFFFFFFu, mx0, 2));
            mx1 = fmaxf(mx1, __shfl_xor_sync(0xFFFFFFFFu, mx1, 1));
            mx1 = fmaxf(mx1, __shfl_xor_sync(0xFFFFFFFFu, mx1, 2));

            const float mn0 = fmaxf(sm0, mx0), mn1 = fmaxf(sm1, mx1);
            const float al0 = __expf(sm0 - mn0), al1 = __expf(sm1 - mn1);
            sm0 = mn0; sm1 = mn1;

            uint32_t pA[8], pB[8];
            float ps0 = 0.f, ps1 = 0.f;
            #pragma unroll
            for (int nb = 0; nb < 8; nb++) {
                const float e0 = __expf(sacc[nb][0] - mn0);
                const float e1 = __expf(sacc[nb][1] - mn0);
                const float e2 = __expf(sacc[nb][2] - mn1);
                const float e3 = __expf(sacc[nb][3] - mn1);
                ps0 += e0 + e1; ps1 += e2 + e3;
                pA[nb] = h2u(__floats2half2_rn(e0, e1));
                pB[nb] = h2u(__floats2half2_rn(e2, e3));
            }
            l0 = l0 * al0 + ps0;
            l1 = l1 * al1 + ps1;

            #pragma unroll
            for (int nb2 = 0; nb2 < 16; nb2++) {
                oacc[nb2][0] *= al0; oacc[nb2][1] *= al0;
                oacc[nb2][2] *= al1; oacc[nb2][3] *= al1;
            }

            #pragma unroll
            for (int kc = 0; kc < 4; kc++) {
                uint32_t a[4] = { pA[2*kc], pB[2*kc], pA[2*kc+1], pB[2*kc+1] };
                const uint32_t kby = (uint32_t)(kc * 32);
                uint32_t bv[16][2];
                #pragma unroll
                for (int np = 0; np < 8; np++)
                    ldsm_x4(bv[2*np][0], bv[2*np][1], bv[2*np+1][0], bv[2*np+1][1],
                            vSt + (uint32_t)(np * 16 * FVP) * 2u + kby);
                #pragma unroll
                for (int nb2 = 0; nb2 < 16; nb2++)
                    mma_f16(oacc[nb2], a, bv[nb2]);
            }
        }
        __syncthreads();
    }

    l0 += __shfl_xor_sync(0xFFFFFFFFu, l0, 1);
    l0 += __shfl_xor_sync(0xFFFFFFFFu, l0, 2);
    l1 += __shfl_xor_sync(0xFFFFFFFFu, l1, 1);
    l1 += __shfl_xor_sync(0xFFFFFFFFu, l1, 2);
    const float inv0 = 1.f / l0, inv1 = 1.f / l1;

    const int b = bh / H_, h = bh % H_;
    __half* out0 = g_ctxh + (size_t)(b * S_ + row0) * (H_*VHD_) + h * VHD_;
    __half* out1 = out0 + (size_t)8 * (H_*VHD_);
    #pragma unroll
    for (int nb2 = 0; nb2 < 16; nb2++) {
        const int d = nb2 * 8 + 2 * tig;
        *(__half2*)(out0 + d) = __floats2half2_rn(oacc[nb2][0] * inv0, oacc[nb2][1] * inv0);
        *(__half2*)(out1 + d) = __floats2half2_rn(oacc[nb2][2] * inv1, oacc[nb2][3] * inv1);
    }
}

// ---------------- converts ----------------
__global__ void cvt_h(const float* __restrict__ src, __half* __restrict__ dst, int n4) {
    int i = blockIdx.x * blockDim.x + threadIdx.x;
    if (i >= n4) return;
    float4 v = ((const float4*)src)[i];
    ((__half2*)dst)[2*i]   = __floats2half2_rn(v.x, v.y);
    ((__half2*)dst)[2*i+1] = __floats2half2_rn(v.z, v.w);
}

__global__ void transpose_h(const float* __restrict__ src, __half* __restrict__ dst,
                            int K, int N, int Npad)
{
    __shared__ float tile[32][33];
    const int k0 = blockIdx.y * 32, n0 = blockIdx.x * 32;
    const int tx = threadIdx.x, ty = threadIdx.y;
    #pragma unroll
    for (int i = ty; i < 32; i += 8) {
        int k = k0 + i, n = n0 + tx;
        tile[i][tx] = (k < K && n < N) ? src[(size_t)k * N + n] : 0.f;
    }
    __syncthreads();
    #pragma unroll
    for (int i = ty; i < 32; i += 8) {
        int n = n0 + i, k = k0 + tx;
        if (n < Npad && k < K) dst[(size_t)n * K + k] = __float2half(tile[tx][i]);
    }
}

// ---------------- fused rmsnorm ----------------
__device__ __forceinline__ float block_reduce_sum(float v, float* sbuf) {
    int tid = threadIdx.x;
    sbuf[tid] = v; __syncthreads();
    #pragma unroll
    for (int s = 128; s > 0; s >>= 1) {
        if (tid < s) sbuf[tid] = sbuf[tid] + sbuf[tid + s];
        __syncthreads();
    }
    float r = sbuf[0]; __syncthreads();
    return r;
}

__global__ __launch_bounds__(256) void rms_both(const float* __restrict__ q_ln,
                                                const float* __restrict__ kv_ln)
{
    __shared__ float sbuf[256];
    const int row = blockIdx.x;
    const float* xr;
    const float* w;
    __half* yr;
    int n;
    if (row < TOK_) {
        xr = g_qa + (size_t)row * QR_; w = q_ln; yr = g_qah + (size_t)row * QR_; n = QR_;
    } else {
        int r = row - TOK_;
        xr = g_kvc + (size_t)r * KVO_; w = kv_ln; yr = g_kvnh + (size_t)r * KVR_; n = KVR_;
    }
    float acc = 0.f;
    for (int j = threadIdx.x; j < n; j += 256) { float v = xr[j]; acc += v * v; }
    float tot = block_reduce_sum(acc, sbuf);
    float scale = rsqrtf(tot / (float)n + EPS_);
    for (int j = threadIdx.x; j < n; j += 256) yr[j] = __float2half(xr[j] * scale * w[j]);
}

// ---------------- RoPE table + K-rope broadcast ----------------
__global__ void build_cs(const int* __restrict__ pos) {
    int idx = blockIdx.x * blockDim.x + threadIdx.x;
    if (idx >= TOK_ * 32) return;
    int j = idx & 31, tok = idx >> 5;
    float inv = powf(10000.f, -((float)(2 * j)) / 64.f);
    float ang = (float)pos[tok] * inv;
    g_cos[idx] = cosf(ang);
    g_sin[idx] = sinf(ang);
}

__global__ void rope_k() {
    int idx = blockIdx.x * blockDim.x + threadIdx.x;
    if (idx >= BH_ * S_ * 32) return;
    int j  = idx & 31;
    int r  = idx >> 5;
    int s  = r % S_;
    int bh = r / S_;
    int b  = bh / H_;
    int tok = b * S_ + s;
    const float* pb = g_kvc + (size_t)tok * KVO_ + KVR_;
    float c = g_cos[tok * 32 + j], sn = g_sin[tok * 32 + j];
    float ev = pb[2*j], ov = pb[2*j + 1];
    *(__half2*)&g_Kfh[((size_t)bh * S_ + s) * QKD_ + NOPE_ + 2*j] =
        __floats2half2_rn(ev * c - ov * sn, ov * c + ev * sn);
}

// ---------------- launcher ----------------
extern "C" void kernel_launch(void* const* d_in, const int* in_sizes, int n_in,
                              void* d_out, int out_size)
{
    const float* hs    = (const float*)d_in[0];
    const float* Wq_a  = (const float*)d_in[1];
    const float* q_ln  = (const float*)d_in[2];
    const float* Wq_b  = (const float*)d_in[3];
    const float* Wkv_a = (const float*)d_in[4];
    const float* kv_ln = (const float*)d_in[5];
    const float* Wkv_b = (const float*)d_in[6];
    const float* Wo    = (const float*)d_in[7];
    const int*   pos   = (const int*)  d_in[8];
    float* out = (float*)d_out;

    float *p_qa, *p_kvc;
    __half *p_ctxh, *p_hsch, *p_wqkvh, *p_wqbh, *p_wkvbh, *p_woh;
    cudaGetSymbolAddress((void**)&p_qa,    g_qa);
    cudaGetSymbolAddress((void**)&p_kvc,   g_kvc);
    cudaGetSymbolAddress((void**)&p_ctxh,  g_ctxh);
    cudaGetSymbolAddress((void**)&p_hsch,  g_hsch);
    cudaGetSymbolAddress((void**)&p_wqkvh, g_wqkvh);
    cudaGetSymbolAddress((void**)&p_wqbh,  g_wqbh);
    cudaGetSymbolAddress((void**)&p_wkvbh, g_wkvbh);
    cudaGetSymbolAddress((void**)&p_woh,   g_woh);

    static bool attr_done = false;
    if (!attr_done) {
        cudaFuncSetAttribute(hgemm<0>, cudaFuncAttributeMaxDynamicSharedMemorySize, SMEM_H);
        cudaFuncSetAttribute(hgemm<2>, cudaFuncAttributeMaxDynamicSharedMemorySize, SMEM_H);
        cudaFuncSetAttribute(hgemm_qkv, cudaFuncAttributeMaxDynamicSharedMemorySize, SMEM_H);
        cudaFuncSetAttribute(flash_attn, cudaFuncAttributeMaxDynamicSharedMemorySize, FSMEM);
        attr_done = true;
    }

    // converts
    cvt_h<<<(TOK_*IN_/4 + 255)/256, 256>>>(hs, p_hsch, TOK_*IN_/4);
    dim3 tb(32, 8);
    transpose_h<<<dim3(QR_/32, IN_/32), tb>>>(Wq_a, p_wqkvh, IN_, QR_, QR_);
    transpose_h<<<dim3((KVO_+31)/32, IN_/32), tb>>>(Wkv_a, p_wqkvh + (size_t)QR_*IN_,
                                                    IN_, KVO_, KVO_);
    transpose_h<<<dim3((H_*QKD_)/32, QR_/32), tb>>>(Wq_b, p_wqbh, QR_, H_*QKD_, H_*QKD_);
    transpose_h<<<dim3((H_*(NOPE_+VHD_))/32, KVR_/32), tb>>>(Wkv_b, p_wkvbh,
                                                             KVR_, H_*(NOPE_+VHD_), H_*(NOPE_+VHD_));
    transpose_h<<<dim3(HID_/32, HID_/32), tb>>>(Wo, p_woh, HID_, HID_, HID_);
    build_cs<<<(TOK_*32 + 255)/256, 256>>>(pos);

    // merged qa + kva projection
    hgemm<2><<<dim3(NQKVP_/128, TOK_/128), 256, SMEM_H>>>(
        p_hsch, p_wqkvh, p_qa, p_kvc, KVO_, QR_,
        TOK_, NQKV_, IN_, IN_, IN_, QR_);

    rms_both<<<2*TOK_, 256>>>(q_ln, kv_ln);
    rope_k<<<(BH_*S_*32 + 255)/256, 256>>>();

    // merged qb + kvb projections (single launch, 1792 CTAs)
    hgemm_qkv<<<dim3(QB_COLS + (H_*(NOPE_+VHD_))/128, TOK_/128), 256, SMEM_H>>>();

    // fused attention
    float scale = 1.f / sqrtf((float)QKD_);
    flash_attn<<<dim3(S_/FBQ, BH_), 256, FSMEM>>>(scale);

    // output projection
    hgemm<0><<<dim3(HID_/128, TOK_/128), 256, SMEM_H>>>(
        p_ctxh, p_woh, out, nullptr, 0, 0,
        TOK_, HID_, HID_, HID_, HID_, HID_);
}

// round 17
// speedup vs baseline: 1.1921x; 1.0432x over previous
#include <cuda_runtime.h>
#include <cuda_fp16.h>
#include <math.h>
#include <stdint.h>

// ---------------- problem constants ----------------
#define B_    2
#define S_    2048
#define HID_  2048
#define IN_   4096
#define H_    16
#define NOPE_ 128
#define ROPE_ 64
#define VHD_  128
#define QKD_  192
#define QR_   1536
#define KVR_  512
#define TOK_  (B_*S_)
#define BH_   (B_*H_)
#define EPS_  1e-6f
#define KVO_  (KVR_+ROPE_)   // 576
#define NQKV_ (QR_+KVO_)     // 2112
#define NQKVP_ 2176
#define QB_COLS ((H_*QKD_)/128)          // 24

// ---------------- scratch ----------------
__device__ float  g_qa  [TOK_*QR_];
__device__ __half g_qah [TOK_*QR_];
__device__ float  g_kvc [TOK_*KVO_];
__device__ __half g_kvnh[TOK_*KVR_];
__device__ __half g_Qfh [BH_*S_*QKD_];
__device__ __half g_Kfh [BH_*S_*QKD_];
__device__ __half g_Vth [BH_*VHD_*S_];             // V^T [bh][d][s]
__device__ __half g_ctxh[TOK_*(H_*VHD_)];
__device__ float  g_cos [TOK_*32];
__device__ float  g_sin [TOK_*32];
__device__ __half g_hsch  [TOK_*IN_];
__device__ __half g_wqkvh [NQKVP_*IN_];
__device__ __half g_wqbh  [(H_*QKD_)*QR_];
__device__ __half g_wkvbh [(H_*(NOPE_+VHD_))*KVR_];
__device__ __half g_woh   [HID_*HID_];

// ---------------- helpers ----------------
__device__ __forceinline__ void mma_f16(float c[4], const uint32_t a[4], const uint32_t b[2]) {
    asm volatile(
        "mma.sync.aligned.m16n8k16.row.col.f32.f16.f16.f32 "
        "{%0,%1,%2,%3}, {%4,%5,%6,%7}, {%8,%9}, {%0,%1,%2,%3};"
        : "+f"(c[0]), "+f"(c[1]), "+f"(c[2]), "+f"(c[3])
        : "r"(a[0]), "r"(a[1]), "r"(a[2]), "r"(a[3]), "r"(b[0]), "r"(b[1]));
}
__device__ __forceinline__ void ldsm_x4(uint32_t& r0, uint32_t& r1, uint32_t& r2, uint32_t& r3,
                                        uint32_t addr) {
    asm volatile("ldmatrix.sync.aligned.m8n8.x4.shared.b16 {%0,%1,%2,%3}, [%4];"
                 : "=r"(r0), "=r"(r1), "=r"(r2), "=r"(r3) : "r"(addr));
}
__device__ __forceinline__ void cp16(uint32_t dst, const void* src) {
    asm volatile("cp.async.cg.shared.global [%0], [%1], 16;\n" :: "r"(dst), "l"(src));
}
__device__ __forceinline__ void cp_commit() {
    asm volatile("cp.async.commit_group;\n" ::: "memory");
}
__device__ __forceinline__ uint32_t h2u(__half2 h) { return *(uint32_t*)&h; }

// ---------------- dense fp16 TB GEMM (R12 shape: 8 warps of 64x32, BK=32, 4 stages) ----------------
#define HBK 32
#define HP  40
#define H_STG (128*HP)
#define HSTG  4
#define SMEM_H (HSTG * 2 * H_STG * 2)

#define GEMM_MAINLOOP(Aptr, Bptr, Kdim, LDA, LDB)                                     \
    const int nt = (Kdim) / HBK;                                                      \
    const int r  = tid >> 1;                                                          \
    const int co = (tid & 1) << 4;                                                    \
    const __half* Ap = (Aptr) + (size_t)(rowBase + r) * (LDA) + co;                   \
    const __half* Bp = (Bptr) + (size_t)(colBase + r) * (LDB) + co;                   \
    const uint32_t a_dst = sA32 + (uint32_t)(r * HP + co) * 2u;                       \
    const uint32_t b_dst = sB32 + (uint32_t)(r * HP + co) * 2u;                       \
    auto load_stage = [&](int st, int kc) {                                           \
        const uint32_t so = (uint32_t)(st * H_STG) * 2u;                              \
        const __half* as = Ap + kc * HBK;                                             \
        const __half* bs = Bp + kc * HBK;                                             \
        cp16(a_dst + so,      as);                                                    \
        cp16(a_dst + so + 16, as + 8);                                                \
        cp16(b_dst + so,      bs);                                                    \
        cp16(b_dst + so + 16, bs + 8);                                                \
        cp_commit();                                                                  \
    };                                                                                \
    const uint32_t aLB = (uint32_t)(((wm * 64 + (lane & 15)) * HP + (lane >> 4) * 8) * 2); \
    const uint32_t bLB = (uint32_t)(((wn * 32 + (lane & 7) + ((lane >> 4) & 1) * 8) * HP   \
                                     + ((lane >> 3) & 1) * 8) * 2);                   \
    _Pragma("unroll")                                                                 \
    for (int s = 0; s < HSTG - 1; s++) {                                              \
        if (s < nt) load_stage(s, s);                                                 \
        else        cp_commit();                                                      \
    }                                                                                 \
    for (int t = 0; t < nt; t++) {                                                    \
        asm volatile("cp.async.wait_group 2;\n" ::: "memory");                        \
        __syncthreads();                                                              \
        const int tn = t + HSTG - 1;                                                  \
        if (tn < nt) load_stage(tn % HSTG, tn);                                       \
        else         cp_commit();                                                     \
        const uint32_t stoff = (uint32_t)((t % HSTG) * H_STG) * 2u;                   \
        const uint32_t aSt = sA32 + stoff + aLB;                                      \
        const uint32_t bSt = sB32 + stoff + bLB;                                      \
        _Pragma("unroll")                                                             \
        for (int ks = 0; ks < 2; ks++) {                                              \
            const uint32_t kby = (uint32_t)(ks * 32);                                 \
            uint32_t afr[4][4], bfr[4][2];                                            \
            _Pragma("unroll")                                                         \
            for (int fm = 0; fm < 4; fm++)                                            \
                ldsm_x4(afr[fm][0], afr[fm][1], afr[fm][2], afr[fm][3],               \
                        aSt + (uint32_t)(fm * 16 * HP) * 2u + kby);                   \
            _Pragma("unroll")                                                         \
            for (int fp = 0; fp < 2; fp++)                                            \
                ldsm_x4(bfr[2*fp][0], bfr[2*fp][1], bfr[2*fp+1][0], bfr[2*fp+1][1],   \
                        bSt + (uint32_t)(fp * 16 * HP) * 2u + kby);                   \
            _Pragma("unroll")                                                         \
            for (int fm = 0; fm < 4; fm++)                                            \
                _Pragma("unroll")                                                     \
                for (int fn = 0; fn < 4; fn++)                                        \
                    mma_f16(acc[fm][fn], afr[fm], bfr[fn]);                           \
        }                                                                             \
    }

// MODE 0: fp32 out; MODE 2: split fp32 out
template<int MODE>
__global__ __launch_bounds__(256, 2) void hgemm(
    const __half* __restrict__ A, const __half* __restrict__ B,
    float* __restrict__ C, float* __restrict__ C2, int ldc2, int nsplit,
    int M, int N, int K, int lda, int ldb, int ldc)
{
    extern __shared__ __half hsm[];
    const uint32_t sA32 = (uint32_t)__cvta_generic_to_shared(hsm);
    const uint32_t sB32 = (uint32_t)__cvta_generic_to_shared(hsm + HSTG * H_STG);

    const int tid  = threadIdx.x;
    const int lane = tid & 31;
    const int g    = lane >> 2;
    const int tig  = lane & 3;
    const int wid  = tid >> 5;
    const int wm   = wid & 1;
    const int wn   = wid >> 1;
    const int rowBase = blockIdx.y * 128;
    const int colBase = blockIdx.x * 128;

    float acc[4][4][4];
    #pragma unroll
    for (int i = 0; i < 4; i++)
        #pragma unroll
        for (int j = 0; j < 4; j++)
            #pragma unroll
            for (int q = 0; q < 4; q++) acc[i][j][q] = 0.f;

    GEMM_MAINLOOP(A, B, K, lda, ldb)

    #pragma unroll
    for (int fm = 0; fm < 4; fm++) {
        #pragma unroll
        for (int fn = 0; fn < 4; fn++) {
            const int row = rowBase + wm * 64 + fm * 16 + g;
            const int col = colBase + wn * 32 + fn * 8 + tig * 2;
            if (col >= N) continue;
            const float a0 = acc[fm][fn][0], a1 = acc[fm][fn][1];
            const float a2 = acc[fm][fn][2], a3 = acc[fm][fn][3];
            if (MODE == 0) {
                *(float2*)&C[(size_t)row * ldc + col]       = make_float2(a0, a1);
                *(float2*)&C[(size_t)(row + 8) * ldc + col] = make_float2(a2, a3);
            } else {
                if (col < nsplit) {
                    *(float2*)&C[(size_t)row * ldc + col]       = make_float2(a0, a1);
                    *(float2*)&C[(size_t)(row + 8) * ldc + col] = make_float2(a2, a3);
                } else {
                    const int c2 = col - nsplit;
                    *(float2*)&C2[(size_t)row * ldc2 + c2]       = make_float2(a0, a1);
                    *(float2*)&C2[(size_t)(row + 8) * ldc2 + c2] = make_float2(a2, a3);
                }
            }
        }
    }
}

// merged qb + kvb projections
__global__ __launch_bounds__(256, 2) void hgemm_qkv()
{
    extern __shared__ __half hsm[];
    const uint32_t sA32 = (uint32_t)__cvta_generic_to_shared(hsm);
    const uint32_t sB32 = (uint32_t)__cvta_generic_to_shared(hsm + HSTG * H_STG);

    const int tid  = threadIdx.x;
    const int lane = tid & 31;
    const int g    = lane >> 2;
    const int tig  = lane & 3;
    const int wid  = tid >> 5;
    const int wm   = wid & 1;
    const int wn   = wid >> 1;
    const int rowBase = blockIdx.y * 128;
    const bool isq = (blockIdx.x < QB_COLS);
    const int colBase = (isq ? blockIdx.x : (blockIdx.x - QB_COLS)) * 128;

    float acc[4][4][4];
    #pragma unroll
    for (int i = 0; i < 4; i++)
        #pragma unroll
        for (int j = 0; j < 4; j++)
            #pragma unroll
            for (int q = 0; q < 4; q++) acc[i][j][q] = 0.f;

    {
        const __half* Asel = isq ? g_qah  : g_kvnh;
        const __half* Bsel = isq ? g_wqbh : g_wkvbh;
        const int Ksel = isq ? QR_ : KVR_;
        GEMM_MAINLOOP(Asel, Bsel, Ksel, Ksel, Ksel)
    }

    #pragma unroll
    for (int fm = 0; fm < 4; fm++) {
        #pragma unroll
        for (int fn = 0; fn < 4; fn++) {
            const int row = rowBase + wm * 64 + fm * 16 + g;
            const int col = colBase + wn * 32 + fn * 8 + tig * 2;   // even
            const float a0 = acc[fm][fn][0], a1 = acc[fm][fn][1];
            const float a2 = acc[fm][fn][2], a3 = acc[fm][fn][3];
            if (isq) {
                const int h = col / QKD_, d = col - h * QKD_;
                #pragma unroll
                for (int rr = 0; rr < 2; rr++) {
                    const int tok = row + rr * 8;
                    const int b = tok >> 11, s = tok & (S_-1);
                    __half* dst = g_Qfh + (((size_t)(b * H_ + h) * S_ + s) * QKD_ + d);
                    const float e = rr ? a2 : a0, o = rr ? a3 : a1;
                    __half2 hv;
                    if (d < NOPE_) {
                        hv = __floats2half2_rn(e, o);
                    } else {
                        const int j = (d - NOPE_) >> 1;
                        const float cc = g_cos[tok * 32 + j], ss = g_sin[tok * 32 + j];
                        hv = __floats2half2_rn(e * cc - o * ss, o * cc + e * ss);
                    }
                    *(__half2*)dst = hv;
                }
            } else {
                const int h = col >> 8, d = col & 255;
                #pragma unroll
                for (int rr = 0; rr < 2; rr++) {
                    const int tok = row + rr * 8;
                    const int b = tok >> 11, s = tok & (S_-1);
                    const int bh = b * H_ + h;
                    const float e = rr ? a2 : a0, o = rr ? a3 : a1;
                    if (d < NOPE_) {
                        *(__half2*)&g_Kfh[((size_t)bh * S_ + s) * QKD_ + d] =
                            __floats2half2_rn(e, o);
                    } else {
                        const int dd = d - NOPE_;
                        __half* vb = g_Vth + ((size_t)bh * VHD_ + dd) * S_ + s;
                        vb[0]  = __float2half(e);
                        vb[S_] = __float2half(o);
                    }
                }
            }
        }
    }
}

// ---------------- fused flash attention (R12: FBQ=128, 256 threads) ----------------
#define FBQ 128
#define FBK 64
#define FQP 200
#define FVP 72
#define FQ_SZ (FBQ*FQP)
#define FK_SZ (FBK*FQP)
#define FV_SZ (VHD_*FVP)
#define FSMEM ((FQ_SZ + 2*FK_SZ + 2*FV_SZ) * 2)

__global__ __launch_bounds__(256, 1) void flash_attn(float scale)
{
    extern __shared__ __half fsm[];
    __half* Qs  = fsm;
    __half* Ks0 = Qs + FQ_SZ;
    __half* Vs0 = Ks0 + 2 * FK_SZ;
    const uint32_t sQ = (uint32_t)__cvta_generic_to_shared(Qs);
    const uint32_t sK = (uint32_t)__cvta_generic_to_shared(Ks0);
    const uint32_t sV = (uint32_t)__cvta_generic_to_shared(Vs0);

    const int qt = (int)(gridDim.x - 1 - blockIdx.x);
    const int bh = blockIdx.y;
    const int qbase = qt * FBQ;
    const int tid = threadIdx.x;
    const int wid = tid >> 5, lane = tid & 31, g = lane >> 2, tig = lane & 3;
    const int qr0 = wid * 16;

    const __half* Qg = g_Qfh + ((size_t)bh * S_ + qbase) * QKD_;
    const __half* Kg = g_Kfh + (size_t)bh * S_ * QKD_;
    const __half* Vg = g_Vth + (size_t)bh * VHD_ * S_;

    {
        int r = tid >> 1, off = (tid & 1) * 96;
        const __half* src = Qg + (size_t)r * QKD_ + off;
        uint32_t dst = sQ + (uint32_t)(r * FQP + off) * 2u;
        #pragma unroll
        for (int c = 0; c < 12; c++) cp16(dst + c * 16, src + c * 8);
    }
    auto loadKV = [&](int st, int kt) {
        const int kbase = kt * FBK;
        {   int r = tid >> 2, off = (tid & 3) * 48;
            const __half* src = Kg + (size_t)(kbase + r) * QKD_ + off;
            uint32_t dst = sK + (uint32_t)(st * FK_SZ + r * FQP + off) * 2u;
            #pragma unroll
            for (int c = 0; c < 6; c++) cp16(dst + c * 16, src + c * 8);
        }
        {   int r = tid >> 1, off = (tid & 1) * 32;
            const __half* src = Vg + (size_t)r * S_ + kbase + off;
            uint32_t dst = sV + (uint32_t)(st * FV_SZ + r * FVP + off) * 2u;
            #pragma unroll
            for (int c = 0; c < 4; c++) cp16(dst + c * 16, src + c * 8);
        }
        cp_commit();
    };

    const int ktmax = (qbase + FBQ - 1) / FBK;
    loadKV(0, 0);

    float oacc[16][4];
    #pragma unroll
    for (int i = 0; i < 16; i++)
        #pragma unroll
        for (int j = 0; j < 4; j++) oacc[i][j] = 0.f;
    float sm0 = -1e30f, sm1 = -1e30f, l0 = 0.f, l1 = 0.f;

    const int row0 = qbase + qr0 + g;
    const int row1 = row0 + 8;

    const uint32_t aQB = sQ + (uint32_t)(((qr0 + (lane & 15)) * FQP + (lane >> 4) * 8) * 2);
    const uint32_t bRow = (uint32_t)((lane & 7) + ((lane >> 4) & 1) * 8);
    const uint32_t bCol = (uint32_t)(((lane >> 3) & 1) * 8);
    const uint32_t bKB = (uint32_t)((bRow * FQP + bCol) * 2);
    const uint32_t bVB = (uint32_t)((bRow * FVP + bCol) * 2);

    for (int kt = 0; kt <= ktmax; kt++) {
        const int st = kt & 1;
        if (kt < ktmax) {
            loadKV(st ^ 1, kt + 1);
            asm volatile("cp.async.wait_group 1;\n" ::: "memory");
        } else {
            asm volatile("cp.async.wait_group 0;\n" ::: "memory");
        }
        __syncthreads();

        const int kbase = kt * FBK;
        if (kbase <= qbase + qr0 + 15) {
            const uint32_t kSt = sK + (uint32_t)(st * FK_SZ) * 2u + bKB;
            const uint32_t vSt = sV + (uint32_t)(st * FV_SZ) * 2u + bVB;

            float sacc[8][4];
            #pragma unroll
            for (int nb = 0; nb < 8; nb++)
                #pragma unroll
                for (int j = 0; j < 4; j++) sacc[nb][j] = 0.f;

            #pragma unroll
            for (int kc = 0; kc < 12; kc++) {
                const uint32_t kby = (uint32_t)(kc * 32);
                uint32_t a[4];
                ldsm_x4(a[0], a[1], a[2], a[3], aQB + kby);
                uint32_t b[8][2];
                #pragma unroll
                for (int np = 0; np < 4; np++)
                    ldsm_x4(b[2*np][0], b[2*np][1], b[2*np+1][0], b[2*np+1][1],
                            kSt + (uint32_t)(np * 16 * FQP) * 2u + kby);
                #pragma unroll
                for (int nb = 0; nb < 8; nb++)
                    mma_f16(sacc[nb], a, b[nb]);
            }

            const bool need_mask = (kbase + FBK - 1) > (qbase + qr0);
            #pragma unroll
            for (int nb = 0; nb < 8; nb++) {
                const int c0 = kbase + nb * 8 + 2 * tig, c1 = c0 + 1;
                sacc[nb][0] *= scale; sacc[nb][1] *= scale;
                sacc[nb][2] *= scale; sacc[nb][3] *= scale;
                if (need_mask) {
                    if (c0 > row0) sacc[nb][0] = -1e30f;
                    if (c1 > row0) sacc[nb][1] = -1e30f;
                    if (c0 > row1) sacc[nb][2] = -1e30f;
                    if (c1 > row1) sacc[nb][3] = -1e30f;
                }
            }

            float mx0 = -1e30f, mx1 = -1e30f;
            #pragma unroll
            for (int nb = 0; nb < 8; nb++) {
                mx0 = fmaxf(mx0, fmaxf(sacc[nb][0], sacc[nb][1]));
                mx1 = fmaxf(mx1, fmaxf(sacc[nb][2], sacc[nb][3]));
            }
            mx0 = fmaxf(mx0, __shfl_xor_sync(0xFFFFFFFFu, mx0, 1));
            mx0 = fmaxf(mx0, __shfl_xor_sync(0xFFFFFFFFu, mx0, 2));
            mx1 = fmaxf(mx1, __shfl_xor_sync(0xFFFFFFFFu, mx1, 1));
            mx1 = fmaxf(mx1, __shfl_xor_sync(0xFFFFFFFFu, mx1, 2));

            const float mn0 = fmaxf(sm0, mx0), mn1 = fmaxf(sm1, mx1);
            const float al0 = __expf(sm0 - mn0), al1 = __expf(sm1 - mn1);
            sm0 = mn0; sm1 = mn1;

            uint32_t pA[8], pB[8];
            float ps0 = 0.f, ps1 = 0.f;
            #pragma unroll
            for (int nb = 0; nb < 8; nb++) {
                const float e0 = __expf(sacc[nb][0] - mn0);
                const float e1 = __expf(sacc[nb][1] - mn0);
                const float e2 = __expf(sacc[nb][2] - mn1);
                const float e3 = __expf(sacc[nb][3] - mn1);
                ps0 += e0 + e1; ps1 += e2 + e3;
                pA[nb] = h2u(__floats2half2_rn(e0, e1));
                pB[nb] = h2u(__floats2half2_rn(e2, e3));
            }
            l0 = l0 * al0 + ps0;
            l1 = l1 * al1 + ps1;

            #pragma unroll
            for (int nb2 = 0; nb2 < 16; nb2++) {
                oacc[nb2][0] *= al0; oacc[nb2][1] *= al0;
                oacc[nb2][2] *= al1; oacc[nb2][3] *= al1;
            }

            #pragma unroll
            for (int kc = 0; kc < 4; kc++) {
                uint32_t a[4] = { pA[2*kc], pB[2*kc], pA[2*kc+1], pB[2*kc+1] };
                const uint32_t kby = (uint32_t)(kc * 32);
                uint32_t bv[16][2];
                #pragma unroll
                for (int np = 0; np < 8; np++)
                    ldsm_x4(bv[2*np][0], bv[2*np][1], bv[2*np+1][0], bv[2*np+1][1],
                            vSt + (uint32_t)(np * 16 * FVP) * 2u + kby);
                #pragma unroll
                for (int nb2 = 0; nb2 < 16; nb2++)
                    mma_f16(oacc[nb2], a, bv[nb2]);
            }
        }
        __syncthreads();
    }

    l0 += __shfl_xor_sync(0xFFFFFFFFu, l0, 1);
    l0 += __shfl_xor_sync(0xFFFFFFFFu, l0, 2);
    l1 += __shfl_xor_sync(0xFFFFFFFFu, l1, 1);
    l1 += __shfl_xor_sync(0xFFFFFFFFu, l1, 2);
    const float inv0 = 1.f / l0, inv1 = 1.f / l1;

    const int b = bh / H_, h = bh % H_;
    __half* out0 = g_ctxh + (size_t)(b * S_ + row0) * (H_*VHD_) + h * VHD_;
    __half* out1 = out0 + (size_t)8 * (H_*VHD_);
    #pragma unroll
    for (int nb2 = 0; nb2 < 16; nb2++) {
        const int d = nb2 * 8 + 2 * tig;
        *(__half2*)(out0 + d) = __floats2half2_rn(oacc[nb2][0] * inv0, oacc[nb2][1] * inv0);
        *(__half2*)(out1 + d) = __floats2half2_rn(oacc[nb2][2] * inv1, oacc[nb2][3] * inv1);
    }
}

// ---------------- unified prologue kernel ----------------
// segment sizes (256-thread blocks)
#define PS_CVT   (TOK_*IN_/4/256)                       // 16384
#define PG_T1    ((QR_/32)*(IN_/32))                    // 6144
#define PG_T2    (((KVO_+31)/32)*(IN_/32))              // 2304
#define PG_T3    (((H_*QKD_)/32)*(QR_/32))              // 4608
#define PG_T4    (((H_*(NOPE_+VHD_))/32)*(KVR_/32))     // 2048
#define PG_T5    ((HID_/32)*(HID_/32))                  // 4096
#define PG_CS    (TOK_*32/256)                          // 512
#define PREP_BLKS (PS_CVT+PG_T1+PG_T2+PG_T3+PG_T4+PG_T5+PG_CS)

__device__ __forceinline__ void tr_tile(const float* __restrict__ src, __half* __restrict__ dst,
                                        int K, int N, int Npad, int bx, int by, int tid)
{
    __shared__ float tile[32][33];
    const int k0 = by * 32, n0 = bx * 32;
    const int tx = tid & 31, ty = tid >> 5;
    #pragma unroll
    for (int i = ty; i < 32; i += 8) {
        int k = k0 + i, n = n0 + tx;
        tile[i][tx] = (k < K && n < N) ? src[(size_t)k * N + n] : 0.f;
    }
    __syncthreads();
    #pragma unroll
    for (int i = ty; i < 32; i += 8) {
        int n = n0 + i, k = k0 + tx;
        if (n < Npad && k < K) dst[(size_t)n * K + k] = __float2half(tile[tx][i]);
    }
}

__global__ __launch_bounds__(256) void prep(
    const float* __restrict__ hs,
    const float* __restrict__ Wq_a, const float* __restrict__ Wkv_a,
    const float* __restrict__ Wq_b, const float* __restrict__ Wkv_b,
    const float* __restrict__ Wo, const int* __restrict__ pos)
{
    int bid = blockIdx.x;
    const int tid = threadIdx.x;

    if (bid < PS_CVT) {
        int i = bid * 256 + tid;
        float4 v = ((const float4*)hs)[i];
        ((__half2*)g_hsch)[2*i]   = __floats2half2_rn(v.x, v.y);
        ((__half2*)g_hsch)[2*i+1] = __floats2half2_rn(v.z, v.w);
        return;
    }
    bid -= PS_CVT;
    if (bid < PG_T1) {
        tr_tile(Wq_a, g_wqkvh, IN_, QR_, QR_, bid % (QR_/32), bid / (QR_/32), tid);
        return;
    }
    bid -= PG_T1;
    if (bid < PG_T2) {
        const int gx = (KVO_+31)/32;
        tr_tile(Wkv_a, g_wqkvh + (size_t)QR_*IN_, IN_, KVO_, KVO_, bid % gx, bid / gx, tid);
        return;
    }
    bid -= PG_T2;
    if (bid < PG_T3) {
        const int gx = (H_*QKD_)/32;
        tr_tile(Wq_b, g_wqbh, QR_, H_*QKD_, H_*QKD_, bid % gx, bid / gx, tid);
        return;
    }
    bid -= PG_T3;
    if (bid < PG_T4) {
        const int gx = (H_*(NOPE_+VHD_))/32;
        tr_tile(Wkv_b, g_wkvbh, KVR_, H_*(NOPE_+VHD_), H_*(NOPE_+VHD_), bid % gx, bid / gx, tid);
        return;
    }
    bid -= PG_T4;
    if (bid < PG_T5) {
        const int gx = HID_/32;
        tr_tile(Wo, g_woh, HID_, HID_, HID_, bid % gx, bid / gx, tid);
        return;
    }
    bid -= PG_T5;
    {   // build_cs
        int idx = bid * 256 + tid;
        int j = idx & 31, tok = idx >> 5;
        float inv = powf(10000.f, -((float)(2 * j)) / 64.f);
        float ang = (float)pos[tok] * inv;
        g_cos[idx] = cosf(ang);
        g_sin[idx] = sinf(ang);
    }
}

// ---------------- fused rmsnorm (+ K-rope broadcast in kv branch) ----------------
__device__ __forceinline__ float block_reduce_sum(float v, float* sbuf) {
    int tid = threadIdx.x;
    sbuf[tid] = v; __syncthreads();
    #pragma unroll
    for (int s = 128; s > 0; s >>= 1) {
        if (tid < s) sbuf[tid] = sbuf[tid] + sbuf[tid + s];
        __syncthreads();
    }
    float r = sbuf[0]; __syncthreads();
    return r;
}

__global__ __launch_bounds__(256) void rms_both(const float* __restrict__ q_ln,
                                                const float* __restrict__ kv_ln)
{
    __shared__ float sbuf[256];
    const int row = blockIdx.x;
    if (row < TOK_) {
        const float* xr = g_qa + (size_t)row * QR_;
        __half* yr = g_qah + (size_t)row * QR_;
        float acc = 0.f;
        for (int j = threadIdx.x; j < QR_; j += 256) { float v = xr[j]; acc += v * v; }
        float tot = block_reduce_sum(acc, sbuf);
        float scale = rsqrtf(tot / (float)QR_ + EPS_);
        for (int j = threadIdx.x; j < QR_; j += 256)
            yr[j] = __float2half(xr[j] * scale * q_ln[j]);
    } else {
        const int tok = row - TOK_;
        const float* xr = g_kvc + (size_t)tok * KVO_;
        __half* yr = g_kvnh + (size_t)tok * KVR_;
        float acc = 0.f;
        for (int j = threadIdx.x; j < KVR_; j += 256) { float v = xr[j]; acc += v * v; }
        float tot = block_reduce_sum(acc, sbuf);
        float scale = rsqrtf(tot / (float)KVR_ + EPS_);
        for (int j = threadIdx.x; j < KVR_; j += 256)
            yr[j] = __float2half(xr[j] * scale * kv_ln[j]);

        // fused K-rope broadcast for this token (identical math to old rope_k)
        const float* pb = xr + KVR_;
        const int j = threadIdx.x & 31;
        const int h = threadIdx.x >> 5;                 // 0..7
        const int b = tok >> 11, s = tok & (S_-1);
        const float c = g_cos[tok * 32 + j], sn = g_sin[tok * 32 + j];
        const float ev = pb[2*j], ov = pb[2*j + 1];
        const __half2 hv = __floats2half2_rn(ev * c - ov * sn, ov * c + ev * sn);
        *(__half2*)&g_Kfh[((size_t)(b * H_ + h)     * S_ + s) * QKD_ + NOPE_ + 2*j] = hv;
        *(__half2*)&g_Kfh[((size_t)(b * H_ + h + 8) * S_ + s) * QKD_ + NOPE_ + 2*j] = hv;
    }
}

// ---------------- launcher ----------------
extern "C" void kernel_launch(void* const* d_in, const int* in_sizes, int n_in,
                              void* d_out, int out_size)
{
    const float* hs    = (const float*)d_in[0];
    const float* Wq_a  = (const float*)d_in[1];
    const float* q_ln  = (const float*)d_in[2];
    const float* Wq_b  = (const float*)d_in[3];
    const float* Wkv_a = (const float*)d_in[4];
    const float* kv_ln = (const float*)d_in[5];
    const float* Wkv_b = (const float*)d_in[6];
    const float* Wo    = (const float*)d_in[7];
    const int*   pos   = (const int*)  d_in[8];
    float* out = (float*)d_out;

    float *p_qa, *p_kvc;
    __half *p_ctxh, *p_hsch, *p_wqkvh, *p_woh;
    cudaGetSymbolAddress((void**)&p_qa,    g_qa);
    cudaGetSymbolAddress((void**)&p_kvc,   g_kvc);
    cudaGetSymbolAddress((void**)&p_ctxh,  g_ctxh);
    cudaGetSymbolAddress((void**)&p_hsch,  g_hsch);
    cudaGetSymbolAddress((void**)&p_wqkvh, g_wqkvh);
    cudaGetSymbolAddress((void**)&p_woh,   g_woh);

    static bool attr_done = false;
    if (!attr_done) {
        cudaFuncSetAttribute(hgemm<0>, cudaFuncAttributeMaxDynamicSharedMemorySize, SMEM_H);
        cudaFuncSetAttribute(hgemm<2>, cudaFuncAttributeMaxDynamicSharedMemorySize, SMEM_H);
        cudaFuncSetAttribute(hgemm_qkv, cudaFuncAttributeMaxDynamicSharedMemorySize, SMEM_H);
        cudaFuncSetAttribute(flash_attn, cudaFuncAttributeMaxDynamicSharedMemorySize, FSMEM);
        attr_done = true;
    }

    // unified prologue: hs convert + all weight transposes + RoPE table
    prep<<<PREP_BLKS, 256>>>(hs, Wq_a, Wkv_a, Wq_b, Wkv_b, Wo, pos);

    // merged qa + kva projection
    hgemm<2><<<dim3(NQKVP_/128, TOK_/128), 256, SMEM_H>>>(
        p_hsch, p_wqkvh, p_qa, p_kvc, KVO_, QR_,
        TOK_, NQKV_, IN_, IN_, IN_, QR_);

    // rmsnorms + fused K-rope
    rms_both<<<2*TOK_, 256>>>(q_ln, kv_ln);

    // merged qb + kvb projections
    hgemm_qkv<<<dim3(QB_COLS + (H_*(NOPE_+VHD_))/128, TOK_/128), 256, SMEM_H>>>();

    // fused attention
    float scale = 1.f / sqrtf((float)QKD_);
    flash_attn<<<dim3(S_/FBQ, BH_), 256, FSMEM>>>(scale);

    // output projection
    hgemm<0><<<dim3(HID_/128, TOK_/128), 256, SMEM_H>>>(
        p_ctxh, p_woh, out, nullptr, 0, 0,
        TOK_, HID_, HID_, HID_, HID_, HID_);
}